// round 1
// baseline (speedup 1.0000x reference)
#include <cuda_runtime.h>
#include <math.h>

#define HW 4096
#define NB 16

// ---------------- scratch (static device globals; no allocation) ----------------
static __device__ float g_tsc [(size_t)NB*256*HW];   // shortcut conv pre-BN
static __device__ float g_h   [(size_t)NB*256*HW];   // W1 conv pre-BN, then h=relu(bn) in place
static __device__ float g_qkv2[(size_t)NB*192*HW];
static __device__ float g_qkv3[(size_t)NB*192*HW];
static __device__ float g_preB[(size_t)NB*256*HW];   // concat of branch pre-BN outputs, then post-BN in place
static __device__ float g_pout[(size_t)NB*256*HW];   // final conv pre-BN
static __device__ float g_ctxp[2*NB*8*4096];         // ctx partials (per n-chunk, deterministic)
static __device__ float g_ctx [2*NB*4096];
static __device__ float g_Mm  [2*NB*4096];           // M = Wproj @ ctx^T per (lga,b)
static __device__ float g_psum  [1024*8];
static __device__ float g_psumsq[1024*8];
static __device__ float g_scale [1024];
static __device__ float g_shift [1024];

// ---------------- batched SGEMM: C[b] = W(b) @ A[b], N=4096 fixed ----------------
// grid: (4096/128, M/64, NB). Block tile 64x128, BK=16, 256 threads, 4x8 microtile.
__global__ __launch_bounds__(256) void gemm_k(
    const float* __restrict__ Wg, const float* __restrict__ A, float* __restrict__ C,
    int K, long wbs, long abs_, int acoff, long cbs, int ccoff)
{
    const int b = blockIdx.z;
    const float* Wp = Wg + (size_t)b * wbs;
    const float* Ap = A + (size_t)b * abs_ + (size_t)acoff * HW;
    float* Cp = C + (size_t)b * cbs + (size_t)ccoff * HW;
    const int n0 = blockIdx.x * 128, m0 = blockIdx.y * 64;

    __shared__ float Ws[16][64];
    __shared__ float Xs[16][128];

    const int tid = threadIdx.x;
    const int tx = tid & 15, ty = tid >> 4;
    const int wm = tid >> 2, wk = (tid & 3) << 2;       // W load: one float4 per thread
    const int xr = tid >> 4, xc = (tid & 15) << 2;      // X load: two float4 per thread

    float acc[4][8];
#pragma unroll
    for (int i = 0; i < 4; i++)
#pragma unroll
        for (int j = 0; j < 8; j++) acc[i][j] = 0.f;

    for (int k0 = 0; k0 < K; k0 += 16) {
        float4 wv = *(const float4*)(Wp + (size_t)(m0 + wm) * K + k0 + wk);
        Ws[wk + 0][wm] = wv.x; Ws[wk + 1][wm] = wv.y;
        Ws[wk + 2][wm] = wv.z; Ws[wk + 3][wm] = wv.w;
        const float* ar = Ap + (size_t)(k0 + xr) * HW + n0;
        *(float4*)&Xs[xr][xc]      = *(const float4*)(ar + xc);
        *(float4*)&Xs[xr][xc + 64] = *(const float4*)(ar + xc + 64);
        __syncthreads();
#pragma unroll
        for (int kk = 0; kk < 16; kk++) {
            float wf[4], xf[8];
            *(float4*)wf       = *(const float4*)&Ws[kk][ty << 2];
            *(float4*)xf       = *(const float4*)&Xs[kk][tx << 3];
            *(float4*)(xf + 4) = *(const float4*)&Xs[kk][(tx << 3) + 4];
#pragma unroll
            for (int i = 0; i < 4; i++)
#pragma unroll
                for (int j = 0; j < 8; j++) acc[i][j] += wf[i] * xf[j];
        }
        __syncthreads();
    }
#pragma unroll
    for (int i = 0; i < 4; i++) {
        float* cr = Cp + (size_t)(m0 + (ty << 2) + i) * HW + n0 + (tx << 3);
        float4 o0 = {acc[i][0], acc[i][1], acc[i][2], acc[i][3]};
        float4 o1 = {acc[i][4], acc[i][5], acc[i][6], acc[i][7]};
        *(float4*)cr = o0; *(float4*)(cr + 4) = o1;
    }
}

// ---------------- per-channel stats (two-stage, deterministic) ----------------
// grid: (C, 8). Each block reduces 8192 of the 65536 (b,hw) samples of channel c.
__global__ __launch_bounds__(256) void stats_k(const float* __restrict__ buf, int C, int slot)
{
    const int c = blockIdx.x, part = blockIdx.y, tid = threadIdx.x;
    const float* p = buf + (size_t)c * HW;
    float s = 0.f, q = 0.f;
    const int i0 = part * 8192;
    for (int i = i0 + tid; i < i0 + 8192; i += 256) {
        int b = i >> 12, off = i & 4095;
        float v = p[(size_t)b * C * HW + off];
        s += v; q += v * v;
    }
    __shared__ float ss[256], sq[256];
    ss[tid] = s; sq[tid] = q; __syncthreads();
    for (int st = 128; st > 0; st >>= 1) {
        if (tid < st) { ss[tid] += ss[tid + st]; sq[tid] += sq[tid + st]; }
        __syncthreads();
    }
    if (tid == 0) {
        g_psum  [(slot + c) * 8 + part] = ss[0];
        g_psumsq[(slot + c) * 8 + part] = sq[0];
    }
}

__global__ void finalize_k(int slot, int C, const float* __restrict__ gamma, const float* __restrict__ beta)
{
    int t = blockIdx.x * blockDim.x + threadIdx.x;
    if (t >= C) return;
    float s = 0.f, q = 0.f;
#pragma unroll
    for (int p = 0; p < 8; p++) { s += g_psum[(slot + t) * 8 + p]; q += g_psumsq[(slot + t) * 8 + p]; }
    const float inv = 1.f / 65536.f;
    float m = s * inv;
    float v = q * inv - m * m;
    float sc = gamma[t] * rsqrtf(v + 1e-5f);
    g_scale[slot + t] = sc;
    g_shift[slot + t] = beta[t] - m * sc;
}

// ---------------- pointwise BN+ReLU in place (C=256 buffers) ----------------
__global__ __launch_bounds__(256) void bnrelu_k(float* __restrict__ buf, int slot)
{
    size_t i = (size_t)blockIdx.x * 256 + threadIdx.x;   // over 4,194,304 float4
    int c = (int)((i >> 10) & 255);                      // HW/4 = 1024
    float sc = g_scale[slot + c], sh = g_shift[slot + c];
    float4 v = ((float4*)buf)[i];
    v.x = fmaxf(v.x * sc + sh, 0.f);
    v.y = fmaxf(v.y * sc + sh, 0.f);
    v.z = fmaxf(v.z * sc + sh, 0.f);
    v.w = fmaxf(v.w * sc + sh, 0.f);
    ((float4*)buf)[i] = v;
}

// ---------------- conv3x3 SAME on s1 (h channels 64..127) -> preB channels 64..127 ----------------
// grid: (4 spatial tiles of 32x32, 16 oc-groups of 4, NB). 256 threads; each thread: 4 oc x 2x2 px.
__global__ __launch_bounds__(256) void conv3_k(const float* __restrict__ Wb1)
{
    __shared__ float sin_[8][34][34];
    __shared__ float sw[4][72];
    const int b = blockIdx.z;
    const int oc0 = blockIdx.y * 4;
    const int ty0 = (blockIdx.x >> 1) * 32, tx0 = (blockIdx.x & 1) * 32;
    const float* in  = g_h    + (size_t)b * 256 * HW + (size_t)64 * HW;
    float*       out = g_preB + (size_t)b * 256 * HW + (size_t)64 * HW;
    const int tid = threadIdx.x;
    const int tx = tid & 15, ty = tid >> 4;

    float acc[4][2][2];
#pragma unroll
    for (int o = 0; o < 4; o++)
#pragma unroll
        for (int i = 0; i < 2; i++)
#pragma unroll
            for (int j = 0; j < 2; j++) acc[o][i][j] = 0.f;

    for (int ic0 = 0; ic0 < 64; ic0 += 8) {
        for (int idx = tid; idx < 8 * 34 * 34; idx += 256) {
            int ic = idx / 1156, r = (idx % 1156) / 34, cc = idx % 34;
            int gy = ty0 + r - 1, gx = tx0 + cc - 1;
            float v = 0.f;
            if ((unsigned)gy < 64u && (unsigned)gx < 64u)
                v = in[(size_t)(ic0 + ic) * HW + gy * 64 + gx];
            sin_[ic][r][cc] = v;
        }
        for (int idx = tid; idx < 288; idx += 256) {
            int oc = idx / 72, r = idx % 72;
            sw[oc][r] = Wb1[(size_t)(oc0 + oc) * 576 + (size_t)ic0 * 9 + r];
        }
        __syncthreads();
#pragma unroll
        for (int ic = 0; ic < 8; ic++) {
#pragma unroll
            for (int t9 = 0; t9 < 9; t9++) {
                const int ky = t9 / 3, kx = t9 % 3;
                float w0 = sw[0][ic * 9 + t9];
                float w1 = sw[1][ic * 9 + t9];
                float w2 = sw[2][ic * 9 + t9];
                float w3 = sw[3][ic * 9 + t9];
#pragma unroll
                for (int iy = 0; iy < 2; iy++) {
                    int y = ty + iy * 16 + ky;
#pragma unroll
                    for (int ix = 0; ix < 2; ix++) {
                        float v = sin_[ic][y][tx + ix * 16 + kx];
                        acc[0][iy][ix] += w0 * v;
                        acc[1][iy][ix] += w1 * v;
                        acc[2][iy][ix] += w2 * v;
                        acc[3][iy][ix] += w3 * v;
                    }
                }
            }
        }
        __syncthreads();
    }
#pragma unroll
    for (int oc = 0; oc < 4; oc++)
#pragma unroll
        for (int iy = 0; iy < 2; iy++)
#pragma unroll
            for (int ix = 0; ix < 2; ix++)
                out[(size_t)(oc0 + oc) * HW + (ty0 + ty + iy * 16) * 64 + tx0 + tx + ix * 16] = acc[oc][iy][ix];
}

// ---------------- softmax over N=4096 on the k-section of qkv, in place ----------------
__global__ __launch_bounds__(256) void softmax_k(float* __restrict__ q2, float* __restrict__ q3)
{
    __shared__ float row[4096];
    __shared__ float red[256];
    const int id = blockIdx.x;                  // 2048 = 2 * 16 * 64
    const int lga = id >> 10, rem = id & 1023;
    const int b = rem >> 6, c = rem & 63;
    float* p = (lga ? q3 : q2) + ((size_t)b * 192 + 64 + c) * HW;
    const int tid = threadIdx.x;

    float m = -1e30f;
    for (int i = tid; i < 4096; i += 256) { float v = p[i]; row[i] = v; m = fmaxf(m, v); }
    red[tid] = m; __syncthreads();
    for (int st = 128; st > 0; st >>= 1) { if (tid < st) red[tid] = fmaxf(red[tid], red[tid + st]); __syncthreads(); }
    m = red[0]; __syncthreads();

    float s = 0.f;
    for (int i = tid; i < 4096; i += 256) { float e = expf(row[i] - m); row[i] = e; s += e; }
    red[tid] = s; __syncthreads();
    for (int st = 128; st > 0; st >>= 1) { if (tid < st) red[tid] += red[tid + st]; __syncthreads(); }
    float inv = 1.f / red[0];
    for (int i = tid; i < 4096; i += 256) p[i] = row[i] * inv;
}

// ---------------- ctx partials: ctx[b,c,d] = sum_n k[c,n]*v[d,n], split over 8 n-chunks ----------------
__global__ __launch_bounds__(256) void ctx_k(const float* __restrict__ q2, const float* __restrict__ q3)
{
    __shared__ float Ks[64][33];
    __shared__ float Vs[64][33];
    const int chunk = blockIdx.x >> 4, b = blockIdx.x & 15, lga = blockIdx.y;
    const float* base = (lga ? q3 : q2) + (size_t)b * 192 * HW;
    const float* kp = base + (size_t)64 * HW;
    const float* vp = base + (size_t)128 * HW;
    const int tid = threadIdx.x;
    const int cb = (tid >> 4) << 2, db = (tid & 15) << 2;

    float acc[4][4];
#pragma unroll
    for (int i = 0; i < 4; i++)
#pragma unroll
        for (int j = 0; j < 4; j++) acc[i][j] = 0.f;

    for (int sub = 0; sub < 16; sub++) {
        const int n0 = chunk * 512 + sub * 32;
        for (int idx = tid; idx < 2048; idx += 256) {
            int r = idx >> 5, cc = idx & 31;
            Ks[r][cc] = kp[(size_t)r * HW + n0 + cc];
            Vs[r][cc] = vp[(size_t)r * HW + n0 + cc];
        }
        __syncthreads();
#pragma unroll 8
        for (int nn = 0; nn < 32; nn++) {
            float kc[4], vd[4];
#pragma unroll
            for (int i = 0; i < 4; i++) { kc[i] = Ks[cb + i][nn]; vd[i] = Vs[db + i][nn]; }
#pragma unroll
            for (int i = 0; i < 4; i++)
#pragma unroll
                for (int j = 0; j < 4; j++) acc[i][j] += kc[i] * vd[j];
        }
        __syncthreads();
    }
    float* cp = g_ctxp + ((size_t)(lga * 16 + b) * 8 + chunk) * 4096;
#pragma unroll
    for (int i = 0; i < 4; i++)
#pragma unroll
        for (int j = 0; j < 4; j++) cp[(cb + i) * 64 + db + j] = acc[i][j];
}

__global__ void ctxred_k()
{
    int i = blockIdx.x * 256 + threadIdx.x;      // 131072 entries
    if (i >= 2 * NB * 4096) return;
    int pair = i >> 12, e = i & 4095;
    const float* cp = g_ctxp + (size_t)pair * 8 * 4096 + e;
    float s = 0.f;
#pragma unroll
    for (int p = 0; p < 8; p++) s += cp[p * 4096];
    g_ctx[i] = s;
}

// ---------------- M[o,c] = sum_d Wproj[o,d] * ctx[c,d]  (so proj(attn) = M @ q, one GEMM) ----------------
__global__ __launch_bounds__(256) void mproj_k(const float* __restrict__ Wp2, const float* __restrict__ Wp3)
{
    const int id = blockIdx.x;                   // 32 = 2 * 16
    const int lga = id >> 4;
    const float* Wp = lga ? Wp3 : Wp2;
    const float* cx = g_ctx + (size_t)id * 4096;
    float* Mo = g_Mm + (size_t)id * 4096;
    for (int e = threadIdx.x; e < 4096; e += 256) {
        int o = e >> 6, c = e & 63;
        float s = 0.f;
#pragma unroll 16
        for (int d = 0; d < 64; d++) s += Wp[o * 64 + d] * cx[c * 64 + d];
        Mo[o * 64 + c] = s;
    }
}

// ---------------- final: out = relu( bn2(pout) + bn_sc(tsc) ) ----------------
__global__ __launch_bounds__(256) void final_k(float* __restrict__ out)
{
    size_t i = (size_t)blockIdx.x * 256 + threadIdx.x;   // over 4,194,304 float4
    int c = (int)((i >> 10) & 255);
    float s2 = g_scale[768 + c], h2 = g_shift[768 + c];
    float s0 = g_scale[c],       h0 = g_shift[c];
    float4 p = ((const float4*)g_pout)[i];
    float4 r = ((const float4*)g_tsc)[i];
    p.x = fmaxf(p.x * s2 + h2 + r.x * s0 + h0, 0.f);
    p.y = fmaxf(p.y * s2 + h2 + r.y * s0 + h0, 0.f);
    p.z = fmaxf(p.z * s2 + h2 + r.z * s0 + h0, 0.f);
    p.w = fmaxf(p.w * s2 + h2 + r.w * s0 + h0, 0.f);
    ((float4*)out)[i] = p;
}

// ---------------- launch ----------------
extern "C" void kernel_launch(void* const* d_in, const int* in_sizes, int n_in,
                              void* d_out, int out_size)
{
    (void)in_sizes; (void)n_in; (void)out_size;
    const float* x      = (const float*)d_in[0];
    const float* W_sc   = (const float*)d_in[1];
    const float* gsc    = (const float*)d_in[2];
    const float* bsc    = (const float*)d_in[3];
    const float* W1     = (const float*)d_in[4];
    const float* g1     = (const float*)d_in[5];
    const float* b1     = (const float*)d_in[6];
    const float* Wb0    = (const float*)d_in[7];
    const float* gb0    = (const float*)d_in[8];
    const float* bb0    = (const float*)d_in[9];
    const float* Wb1    = (const float*)d_in[10];
    const float* gb1    = (const float*)d_in[11];
    const float* bb1    = (const float*)d_in[12];
    const float* Wqkv2  = (const float*)d_in[13];
    const float* Wproj2 = (const float*)d_in[14];
    const float* ga2    = (const float*)d_in[15];
    const float* ba2    = (const float*)d_in[16];
    const float* Wqkv3  = (const float*)d_in[17];
    const float* Wproj3 = (const float*)d_in[18];
    const float* ga3    = (const float*)d_in[19];
    const float* ba3    = (const float*)d_in[20];
    const float* W2     = (const float*)d_in[21];
    const float* g2     = (const float*)d_in[22];
    const float* b2     = (const float*)d_in[23];

    float *tsc, *hh, *qk2, *qk3, *preB, *pout, *Mm;
    cudaGetSymbolAddress((void**)&tsc,  g_tsc);
    cudaGetSymbolAddress((void**)&hh,   g_h);
    cudaGetSymbolAddress((void**)&qk2,  g_qkv2);
    cudaGetSymbolAddress((void**)&qk3,  g_qkv3);
    cudaGetSymbolAddress((void**)&preB, g_preB);
    cudaGetSymbolAddress((void**)&pout, g_pout);
    cudaGetSymbolAddress((void**)&Mm,   g_Mm);

    // Stage 1: the two 128->256 convs over x
    gemm_k<<<dim3(32, 4, NB), 256>>>(W_sc, x, tsc, 128, 0, (long)128 * HW, 0, (long)256 * HW, 0);
    gemm_k<<<dim3(32, 4, NB), 256>>>(W1,   x, hh,  128, 0, (long)128 * HW, 0, (long)256 * HW, 0);
    stats_k<<<dim3(256, 8), 256>>>(tsc, 256, 0);
    stats_k<<<dim3(256, 8), 256>>>(hh,  256, 256);
    finalize_k<<<1, 256>>>(0,   256, gsc, bsc);
    finalize_k<<<1, 256>>>(256, 256, g1,  b1);
    bnrelu_k<<<16384, 256>>>(hh, 256);                       // h = relu(bn(.)) in place

    // Branch 0: 1x1 conv on s0 -> preB ch 0..63
    gemm_k<<<dim3(32, 1, NB), 256>>>(Wb0, hh, preB, 64, 0, (long)256 * HW, 0, (long)256 * HW, 0);
    // Branch 1: 3x3 conv on s1 -> preB ch 64..127
    conv3_k<<<dim3(4, 16, NB), 256>>>(Wb1);
    // Branches 2/3: qkv projections on s2/s3
    gemm_k<<<dim3(32, 3, NB), 256>>>(Wqkv2, hh, qk2, 64, 0, (long)256 * HW, 128, (long)192 * HW, 0);
    gemm_k<<<dim3(32, 3, NB), 256>>>(Wqkv3, hh, qk3, 64, 0, (long)256 * HW, 192, (long)192 * HW, 0);
    softmax_k<<<2048, 256>>>(qk2, qk3);
    ctx_k<<<dim3(128, 2), 256>>>(qk2, qk3);
    ctxred_k<<<512, 256>>>();
    mproj_k<<<32, 256>>>(Wproj2, Wproj3);
    // attn output fused with proj: preB ch 128..191 / 192..255 = M[b] @ q[b]
    gemm_k<<<dim3(32, 1, NB), 256>>>(Mm,                 qk2, preB, 64, 4096, (long)192 * HW, 0, (long)256 * HW, 128);
    gemm_k<<<dim3(32, 1, NB), 256>>>(Mm + (size_t)NB*4096, qk3, preB, 64, 4096, (long)192 * HW, 0, (long)256 * HW, 192);

    // Branch BNs + ReLU (in place on preB -> concat input)
    stats_k<<<dim3(256, 8), 256>>>(preB, 256, 512);
    finalize_k<<<1, 64>>>(512, 64, gb0, bb0);
    finalize_k<<<1, 64>>>(576, 64, gb1, bb1);
    finalize_k<<<1, 64>>>(640, 64, ga2, ba2);
    finalize_k<<<1, 64>>>(704, 64, ga3, ba3);
    bnrelu_k<<<16384, 256>>>(preB, 512);

    // Final 256->256 conv, its BN, + shortcut BN + ReLU
    gemm_k<<<dim3(32, 4, NB), 256>>>(W2, preB, pout, 256, 0, (long)256 * HW, 0, (long)256 * HW, 0);
    stats_k<<<dim3(256, 8), 256>>>(pout, 256, 768);
    finalize_k<<<1, 256>>>(768, 256, g2, b2);
    final_k<<<16384, 256>>>((float*)d_out);
}

// round 3
// speedup vs baseline: 1.1933x; 1.1933x over previous
#include <cuda_runtime.h>
#include <cstdint>
#include <math.h>

#define HW 4096
#define NB 16
#define BK 32

// ---------------- scratch (static device globals; no allocation) ----------------
static __device__ float g_tsc [(size_t)NB*256*HW];
static __device__ float g_h   [(size_t)NB*256*HW];
static __device__ float g_qkv2[(size_t)NB*192*HW];
static __device__ float g_qkv3[(size_t)NB*192*HW];
static __device__ float g_preB[(size_t)NB*256*HW];
static __device__ float g_pout[(size_t)NB*256*HW];
static __device__ float g_ctxp[2*NB*8*4096];
static __device__ float g_ctx [2*NB*4096];
static __device__ float g_Mm  [2*NB*4096];
static __device__ float g_psum  [1024*8];
static __device__ float g_psumsq[1024*8];
static __device__ float g_scale [1024];
static __device__ float g_shift [1024];

__device__ __forceinline__ uint32_t to_tf32(float x) {
    uint32_t y; asm("cvt.rna.tf32.f32 %0, %1;" : "=r"(y) : "f"(x)); return y;
}
__device__ __forceinline__ void mma8(float* c, const uint32_t* a, const uint32_t* b) {
    asm volatile("mma.sync.aligned.m16n8k8.row.col.f32.tf32.tf32.f32 "
        "{%0,%1,%2,%3}, {%4,%5,%6,%7}, {%8,%9}, {%0,%1,%2,%3};"
        : "+f"(c[0]), "+f"(c[1]), "+f"(c[2]), "+f"(c[3])
        : "r"(a[0]), "r"(a[1]), "r"(a[2]), "r"(a[3]), "r"(b[0]), "r"(b[1]));
}

// dynamic smem layout (floats): A[2][128*36], B[2][32*132]
#define AS_OFF(buf) ((buf) * 4608)
#define BS_OFF(buf) (9216 + (buf) * 4224)
#define SMEMSZ (17664 * 4)

// ---------------- tf32 mma.sync batched GEMM: C[b] = W(b) @ A[b], N=4096 ----------------
// grid: (32, ceil(M/128), NB), 256 threads. Block tile 128x128, BK=32.
__global__ __launch_bounds__(256) void tgemm_k(
    const float* __restrict__ Wg, const float* __restrict__ A, float* __restrict__ C,
    int K, int Mrows, long wbs, long abs_, int acoff, long cbs, int ccoff)
{
    extern __shared__ float sm[];
    const int b = blockIdx.z;
    const float* Wp = Wg + (size_t)b * wbs;
    const float* Ap = A + (size_t)b * abs_ + (size_t)acoff * HW;
    float* Cp = C + (size_t)b * cbs + (size_t)ccoff * HW;
    const int n0 = blockIdx.x * 128, m0 = blockIdx.y * 128;
    const int tid = threadIdx.x, lane = tid & 31, wid = tid >> 5;
    const int wm0 = (wid >> 2) * 64, wn0 = (wid & 3) * 32;
    const int qr = lane >> 2, qc = lane & 3;

    // fill indices
    const int fam = tid >> 1, fac = (tid & 1) * 16;          // A: row fam, 16 floats from fac
    const int fbk = tid >> 3, fbc = (tid & 7) * 16;          // B: k-row fbk, 16 floats from fbc
    const bool avalid = (m0 + fam) < Mrows;
    const int nk = K / BK;

    float acc[4][4][4];
#pragma unroll
    for (int i = 0; i < 4; i++)
#pragma unroll
        for (int j = 0; j < 4; j++)
#pragma unroll
            for (int e = 0; e < 4; e++) acc[i][j][e] = 0.f;

    float4 pa[4], pb[4];
    // prefetch chunk 0
    {
        const float* wr = Wp + (size_t)(m0 + fam) * K + fac;
        const float* br = Ap + (size_t)fbk * HW + n0 + fbc;
#pragma unroll
        for (int t = 0; t < 4; t++) {
            pa[t] = avalid ? *(const float4*)(wr + t * 4) : make_float4(0.f, 0.f, 0.f, 0.f);
            pb[t] = *(const float4*)(br + t * 4);
        }
    }
    // store chunk 0
    {
        float* as = sm + AS_OFF(0) + fam * 36 + fac;
        float* bs = sm + BS_OFF(0) + fbk * 132 + fbc;
#pragma unroll
        for (int t = 0; t < 4; t++) {
            ((uint32_t*)as)[t*4+0] = to_tf32(pa[t].x); ((uint32_t*)as)[t*4+1] = to_tf32(pa[t].y);
            ((uint32_t*)as)[t*4+2] = to_tf32(pa[t].z); ((uint32_t*)as)[t*4+3] = to_tf32(pa[t].w);
            ((uint32_t*)bs)[t*4+0] = to_tf32(pb[t].x); ((uint32_t*)bs)[t*4+1] = to_tf32(pb[t].y);
            ((uint32_t*)bs)[t*4+2] = to_tf32(pb[t].z); ((uint32_t*)bs)[t*4+3] = to_tf32(pb[t].w);
        }
    }
    __syncthreads();

    for (int kc = 0; kc < nk; kc++) {
        const int cur = kc & 1;
        if (kc + 1 < nk) {
            const float* wr = Wp + (size_t)(m0 + fam) * K + (kc + 1) * BK + fac;
            const float* br = Ap + (size_t)((kc + 1) * BK + fbk) * HW + n0 + fbc;
#pragma unroll
            for (int t = 0; t < 4; t++) {
                pa[t] = avalid ? *(const float4*)(wr + t * 4) : make_float4(0.f, 0.f, 0.f, 0.f);
                pb[t] = *(const float4*)(br + t * 4);
            }
        }
        const uint32_t* as = (const uint32_t*)(sm + AS_OFF(cur));
        const uint32_t* bs = (const uint32_t*)(sm + BS_OFF(cur));
#pragma unroll
        for (int ks = 0; ks < 4; ks++) {
            uint32_t af[4][4], bf[4][2];
            const int kk = ks * 8 + qc;
#pragma unroll
            for (int mt = 0; mt < 4; mt++) {
                const uint32_t* ap = as + (wm0 + mt * 16 + qr) * 36 + kk;
                af[mt][0] = ap[0];
                af[mt][1] = ap[8 * 36];
                af[mt][2] = ap[4];
                af[mt][3] = ap[8 * 36 + 4];
            }
#pragma unroll
            for (int nt = 0; nt < 4; nt++) {
                const uint32_t* bp = bs + kk * 132 + wn0 + nt * 8 + qr;
                bf[nt][0] = bp[0];
                bf[nt][1] = bp[4 * 132];
            }
#pragma unroll
            for (int mt = 0; mt < 4; mt++)
#pragma unroll
                for (int nt = 0; nt < 4; nt++) mma8(acc[mt][nt], af[mt], bf[nt]);
        }
        if (kc + 1 < nk) {
            const int nxt = cur ^ 1;
            float* das = sm + AS_OFF(nxt) + fam * 36 + fac;
            float* dbs = sm + BS_OFF(nxt) + fbk * 132 + fbc;
#pragma unroll
            for (int t = 0; t < 4; t++) {
                ((uint32_t*)das)[t*4+0] = to_tf32(pa[t].x); ((uint32_t*)das)[t*4+1] = to_tf32(pa[t].y);
                ((uint32_t*)das)[t*4+2] = to_tf32(pa[t].z); ((uint32_t*)das)[t*4+3] = to_tf32(pa[t].w);
                ((uint32_t*)dbs)[t*4+0] = to_tf32(pb[t].x); ((uint32_t*)dbs)[t*4+1] = to_tf32(pb[t].y);
                ((uint32_t*)dbs)[t*4+2] = to_tf32(pb[t].z); ((uint32_t*)dbs)[t*4+3] = to_tf32(pb[t].w);
            }
        }
        __syncthreads();
    }

#pragma unroll
    for (int mt = 0; mt < 4; mt++) {
        const int m = m0 + wm0 + mt * 16 + qr;
#pragma unroll
        for (int nt = 0; nt < 4; nt++) {
            const int n = n0 + wn0 + nt * 8 + qc * 2;
            if (m < Mrows)
                *(float2*)(Cp + (size_t)m * HW + n) = make_float2(acc[mt][nt][0], acc[mt][nt][1]);
            if (m + 8 < Mrows)
                *(float2*)(Cp + (size_t)(m + 8) * HW + n) = make_float2(acc[mt][nt][2], acc[mt][nt][3]);
        }
    }
}

// ---------------- tf32 mma.sync implicit-GEMM 3x3 conv on s1 ----------------
// out ch 64..127 of preB; in ch 64..127 of h. K = 576 = 9 taps * 64 ic, 18 chunks.
__global__ __launch_bounds__(256) void tconv_k(const float* __restrict__ Wb1)
{
    extern __shared__ float sm[];
    const int b = blockIdx.z;
    const float* Ap = g_h + (size_t)b * 256 * HW + (size_t)64 * HW;
    float* Cp = g_preB + (size_t)b * 256 * HW + (size_t)64 * HW;
    const int n0 = blockIdx.x * 128;
    const int tid = threadIdx.x, lane = tid & 31, wid = tid >> 5;
    const int wm0 = (wid >> 2) * 64, wn0 = (wid & 3) * 32;
    const int qr = lane >> 2, qc = lane & 3;
    const int fam = tid >> 1, fac = (tid & 1) * 16;
    const int fbk = tid >> 3, fbc = (tid & 7) * 16;
    const int nk = 18;

    float acc[4][4][4];
#pragma unroll
    for (int i = 0; i < 4; i++)
#pragma unroll
        for (int j = 0; j < 4; j++)
#pragma unroll
            for (int e = 0; e < 4; e++) acc[i][j][e] = 0.f;

    float pa[16], pb[16];
    // loader: A[m][klocal] = (m<64) ? Wb1[m*576 + ic*9 + tap] : 0, ic = half*32 + klocal
    // B[k][n] = plane[ic][y+dy][x+dx] masked
    auto loadA = [&](int kc) {
        const int tap = kc >> 1, half = kc & 1;
#pragma unroll
        for (int s = 0; s < 16; s++) {
            float v = 0.f;
            if (fam < 64) {
                int ic = half * 32 + fac + s;
                v = Wb1[(size_t)fam * 576 + (size_t)ic * 9 + tap];
            }
            pa[s] = v;
        }
    };
    auto loadB = [&](int kc) {
        const int tap = kc >> 1, half = kc & 1;
        const int dy = tap / 3 - 1, dx = tap % 3 - 1;
        const int ic = half * 32 + fbk;
        const float* plane = Ap + (size_t)ic * HW;
#pragma unroll
        for (int s = 0; s < 16; s++) {
            int p = n0 + fbc + s;
            int y = (p >> 6) + dy, x = (p & 63) + dx;
            float v = 0.f;
            if ((unsigned)y < 64u && (unsigned)x < 64u) v = plane[y * 64 + x];
            pb[s] = v;
        }
    };
    auto storeT = [&](int buf) {
        uint32_t* das = (uint32_t*)(sm + AS_OFF(buf)) + fam * 36 + fac;
        uint32_t* dbs = (uint32_t*)(sm + BS_OFF(buf)) + fbk * 132 + fbc;
#pragma unroll
        for (int s = 0; s < 16; s++) { das[s] = to_tf32(pa[s]); dbs[s] = to_tf32(pb[s]); }
    };

    loadA(0); loadB(0); storeT(0);
    __syncthreads();

    for (int kc = 0; kc < nk; kc++) {
        const int cur = kc & 1;
        if (kc + 1 < nk) { loadA(kc + 1); loadB(kc + 1); }
        const uint32_t* as = (const uint32_t*)(sm + AS_OFF(cur));
        const uint32_t* bs = (const uint32_t*)(sm + BS_OFF(cur));
#pragma unroll
        for (int ks = 0; ks < 4; ks++) {
            uint32_t af[4][4], bf[4][2];
            const int kk = ks * 8 + qc;
#pragma unroll
            for (int mt = 0; mt < 4; mt++) {
                const uint32_t* ap = as + (wm0 + mt * 16 + qr) * 36 + kk;
                af[mt][0] = ap[0];
                af[mt][1] = ap[8 * 36];
                af[mt][2] = ap[4];
                af[mt][3] = ap[8 * 36 + 4];
            }
#pragma unroll
            for (int nt = 0; nt < 4; nt++) {
                const uint32_t* bp = bs + kk * 132 + wn0 + nt * 8 + qr;
                bf[nt][0] = bp[0];
                bf[nt][1] = bp[4 * 132];
            }
#pragma unroll
            for (int mt = 0; mt < 4; mt++)
#pragma unroll
                for (int nt = 0; nt < 4; nt++) mma8(acc[mt][nt], af[mt], bf[nt]);
        }
        if (kc + 1 < nk) storeT(cur ^ 1);
        __syncthreads();
    }

#pragma unroll
    for (int mt = 0; mt < 4; mt++) {
        const int m = wm0 + mt * 16 + qr;
#pragma unroll
        for (int nt = 0; nt < 4; nt++) {
            const int n = n0 + wn0 + nt * 8 + qc * 2;
            if (m < 64)
                *(float2*)(Cp + (size_t)m * HW + n) = make_float2(acc[mt][nt][0], acc[mt][nt][1]);
            if (m + 8 < 64)
                *(float2*)(Cp + (size_t)(m + 8) * HW + n) = make_float2(acc[mt][nt][2], acc[mt][nt][3]);
        }
    }
}

// ---------------- per-channel stats (two-stage, deterministic) ----------------
__global__ __launch_bounds__(256) void stats_k(const float* __restrict__ buf, int C, int slot)
{
    const int c = blockIdx.x, part = blockIdx.y, tid = threadIdx.x;
    const float* p = buf + (size_t)c * HW;
    float s = 0.f, q = 0.f;
    const int i0 = part * 8192;
    for (int i = i0 + tid; i < i0 + 8192; i += 256) {
        int b = i >> 12, off = i & 4095;
        float v = p[(size_t)b * C * HW + off];
        s += v; q += v * v;
    }
    __shared__ float ss[256], sq[256];
    ss[tid] = s; sq[tid] = q; __syncthreads();
    for (int st = 128; st > 0; st >>= 1) {
        if (tid < st) { ss[tid] += ss[tid + st]; sq[tid] += sq[tid + st]; }
        __syncthreads();
    }
    if (tid == 0) {
        g_psum  [(slot + c) * 8 + part] = ss[0];
        g_psumsq[(slot + c) * 8 + part] = sq[0];
    }
}

__global__ void finalize_k(int slot, int C, const float* __restrict__ gamma, const float* __restrict__ beta)
{
    int t = blockIdx.x * blockDim.x + threadIdx.x;
    if (t >= C) return;
    float s = 0.f, q = 0.f;
#pragma unroll
    for (int p = 0; p < 8; p++) { s += g_psum[(slot + t) * 8 + p]; q += g_psumsq[(slot + t) * 8 + p]; }
    const float inv = 1.f / 65536.f;
    float m = s * inv;
    float v = q * inv - m * m;
    float sc = gamma[t] * rsqrtf(v + 1e-5f);
    g_scale[slot + t] = sc;
    g_shift[slot + t] = beta[t] - m * sc;
}

// ---------------- pointwise BN+ReLU in place ----------------
__global__ __launch_bounds__(256) void bnrelu_k(float* __restrict__ buf, int slot)
{
    size_t i = (size_t)blockIdx.x * 256 + threadIdx.x;
    int c = (int)((i >> 10) & 255);
    float sc = g_scale[slot + c], sh = g_shift[slot + c];
    float4 v = ((float4*)buf)[i];
    v.x = fmaxf(v.x * sc + sh, 0.f);
    v.y = fmaxf(v.y * sc + sh, 0.f);
    v.z = fmaxf(v.z * sc + sh, 0.f);
    v.w = fmaxf(v.w * sc + sh, 0.f);
    ((float4*)buf)[i] = v;
}

// ---------------- softmax over N=4096 on the k-section of qkv ----------------
__global__ __launch_bounds__(256) void softmax_k(float* __restrict__ q2, float* __restrict__ q3)
{
    __shared__ float row[4096];
    __shared__ float red[256];
    const int id = blockIdx.x;
    const int lga = id >> 10, rem = id & 1023;
    const int b = rem >> 6, c = rem & 63;
    float* p = (lga ? q3 : q2) + ((size_t)b * 192 + 64 + c) * HW;
    const int tid = threadIdx.x;

    float m = -1e30f;
    for (int i = tid; i < 4096; i += 256) { float v = p[i]; row[i] = v; m = fmaxf(m, v); }
    red[tid] = m; __syncthreads();
    for (int st = 128; st > 0; st >>= 1) { if (tid < st) red[tid] = fmaxf(red[tid], red[tid + st]); __syncthreads(); }
    m = red[0]; __syncthreads();

    float s = 0.f;
    for (int i = tid; i < 4096; i += 256) { float e = expf(row[i] - m); row[i] = e; s += e; }
    red[tid] = s; __syncthreads();
    for (int st = 128; st > 0; st >>= 1) { if (tid < st) red[tid] += red[tid + st]; __syncthreads(); }
    float inv = 1.f / red[0];
    for (int i = tid; i < 4096; i += 256) p[i] = row[i] * inv;
}

// ---------------- ctx partials: ctx[b,c,d] = sum_n k[c,n]*v[d,n] ----------------
__global__ __launch_bounds__(256) void ctx_k(const float* __restrict__ q2, const float* __restrict__ q3)
{
    __shared__ float Ks[64][33];
    __shared__ float Vs[64][33];
    const int chunk = blockIdx.x >> 4, b = blockIdx.x & 15, lga = blockIdx.y;
    const float* base = (lga ? q3 : q2) + (size_t)b * 192 * HW;
    const float* kp = base + (size_t)64 * HW;
    const float* vp = base + (size_t)128 * HW;
    const int tid = threadIdx.x;
    const int cb = (tid >> 4) << 2, db = (tid & 15) << 2;

    float acc[4][4];
#pragma unroll
    for (int i = 0; i < 4; i++)
#pragma unroll
        for (int j = 0; j < 4; j++) acc[i][j] = 0.f;

    for (int sub = 0; sub < 16; sub++) {
        const int n0 = chunk * 512 + sub * 32;
        for (int idx = tid; idx < 2048; idx += 256) {
            int r = idx >> 5, cc = idx & 31;
            Ks[r][cc] = kp[(size_t)r * HW + n0 + cc];
            Vs[r][cc] = vp[(size_t)r * HW + n0 + cc];
        }
        __syncthreads();
#pragma unroll 8
        for (int nn = 0; nn < 32; nn++) {
            float kc[4], vd[4];
#pragma unroll
            for (int i = 0; i < 4; i++) { kc[i] = Ks[cb + i][nn]; vd[i] = Vs[db + i][nn]; }
#pragma unroll
            for (int i = 0; i < 4; i++)
#pragma unroll
                for (int j = 0; j < 4; j++) acc[i][j] += kc[i] * vd[j];
        }
        __syncthreads();
    }
    float* cp = g_ctxp + ((size_t)(lga * 16 + b) * 8 + chunk) * 4096;
#pragma unroll
    for (int i = 0; i < 4; i++)
#pragma unroll
        for (int j = 0; j < 4; j++) cp[(cb + i) * 64 + db + j] = acc[i][j];
}

__global__ void ctxred_k()
{
    int i = blockIdx.x * 256 + threadIdx.x;
    if (i >= 2 * NB * 4096) return;
    int pair = i >> 12, e = i & 4095;
    const float* cp = g_ctxp + (size_t)pair * 8 * 4096 + e;
    float s = 0.f;
#pragma unroll
    for (int p = 0; p < 8; p++) s += cp[p * 4096];
    g_ctx[i] = s;
}

// ---------------- M[o,c] = sum_d Wproj[o,d] * ctx[c,d] ----------------
__global__ __launch_bounds__(256) void mproj_k(const float* __restrict__ Wp2, const float* __restrict__ Wp3)
{
    const int id = blockIdx.x;
    const int lga = id >> 4;
    const float* Wp = lga ? Wp3 : Wp2;
    const float* cx = g_ctx + (size_t)id * 4096;
    float* Mo = g_Mm + (size_t)id * 4096;
    for (int e = threadIdx.x; e < 4096; e += 256) {
        int o = e >> 6, c = e & 63;
        float s = 0.f;
#pragma unroll 16
        for (int d = 0; d < 64; d++) s += Wp[o * 64 + d] * cx[c * 64 + d];
        Mo[o * 64 + c] = s;
    }
}

// ---------------- final: out = relu( bn2(pout) + bn_sc(tsc) ) ----------------
__global__ __launch_bounds__(256) void final_k(float* __restrict__ out)
{
    size_t i = (size_t)blockIdx.x * 256 + threadIdx.x;
    int c = (int)((i >> 10) & 255);
    float s2 = g_scale[768 + c], h2 = g_shift[768 + c];
    float s0 = g_scale[c],       h0 = g_shift[c];
    float4 p = ((const float4*)g_pout)[i];
    float4 r = ((const float4*)g_tsc)[i];
    p.x = fmaxf(p.x * s2 + h2 + r.x * s0 + h0, 0.f);
    p.y = fmaxf(p.y * s2 + h2 + r.y * s0 + h0, 0.f);
    p.z = fmaxf(p.z * s2 + h2 + r.z * s0 + h0, 0.f);
    p.w = fmaxf(p.w * s2 + h2 + r.w * s0 + h0, 0.f);
    ((float4*)out)[i] = p;
}

// ---------------- launch ----------------
extern "C" void kernel_launch(void* const* d_in, const int* in_sizes, int n_in,
                              void* d_out, int out_size)
{
    (void)in_sizes; (void)n_in; (void)out_size;
    const float* x      = (const float*)d_in[0];
    const float* W_sc   = (const float*)d_in[1];
    const float* gsc    = (const float*)d_in[2];
    const float* bsc    = (const float*)d_in[3];
    const float* W1     = (const float*)d_in[4];
    const float* g1     = (const float*)d_in[5];
    const float* b1     = (const float*)d_in[6];
    const float* Wb0    = (const float*)d_in[7];
    const float* gb0    = (const float*)d_in[8];
    const float* bb0    = (const float*)d_in[9];
    const float* Wb1    = (const float*)d_in[10];
    const float* gb1    = (const float*)d_in[11];
    const float* bb1    = (const float*)d_in[12];
    const float* Wqkv2  = (const float*)d_in[13];
    const float* Wproj2 = (const float*)d_in[14];
    const float* ga2    = (const float*)d_in[15];
    const float* ba2    = (const float*)d_in[16];
    const float* Wqkv3  = (const float*)d_in[17];
    const float* Wproj3 = (const float*)d_in[18];
    const float* ga3    = (const float*)d_in[19];
    const float* ba3    = (const float*)d_in[20];
    const float* W2     = (const float*)d_in[21];
    const float* g2     = (const float*)d_in[22];
    const float* b2     = (const float*)d_in[23];

    static int attr_done = 0;
    if (!attr_done) {
        cudaFuncSetAttribute(tgemm_k, cudaFuncAttributeMaxDynamicSharedMemorySize, SMEMSZ);
        cudaFuncSetAttribute(tconv_k, cudaFuncAttributeMaxDynamicSharedMemorySize, SMEMSZ);
        attr_done = 1;
    }

    float *tsc, *hh, *qk2, *qk3, *preB, *pout, *Mm;
    cudaGetSymbolAddress((void**)&tsc,  g_tsc);
    cudaGetSymbolAddress((void**)&hh,   g_h);
    cudaGetSymbolAddress((void**)&qk2,  g_qkv2);
    cudaGetSymbolAddress((void**)&qk3,  g_qkv3);
    cudaGetSymbolAddress((void**)&preB, g_preB);
    cudaGetSymbolAddress((void**)&pout, g_pout);
    cudaGetSymbolAddress((void**)&Mm,   g_Mm);

    // Stage 1: the two 128->256 convs over x
    tgemm_k<<<dim3(32, 2, NB), 256, SMEMSZ>>>(W_sc, x, tsc, 128, 256, 0, (long)128 * HW, 0, (long)256 * HW, 0);
    tgemm_k<<<dim3(32, 2, NB), 256, SMEMSZ>>>(W1,   x, hh,  128, 256, 0, (long)128 * HW, 0, (long)256 * HW, 0);
    stats_k<<<dim3(256, 8), 256>>>(tsc, 256, 0);
    stats_k<<<dim3(256, 8), 256>>>(hh,  256, 256);
    finalize_k<<<1, 256>>>(0,   256, gsc, bsc);
    finalize_k<<<1, 256>>>(256, 256, g1,  b1);
    bnrelu_k<<<16384, 256>>>(hh, 256);

    // Branch 0: 1x1 conv on s0 -> preB ch 0..63
    tgemm_k<<<dim3(32, 1, NB), 256, SMEMSZ>>>(Wb0, hh, preB, 64, 64, 0, (long)256 * HW, 0, (long)256 * HW, 0);
    // Branch 1: 3x3 conv on s1 -> preB ch 64..127 (implicit GEMM)
    tconv_k<<<dim3(32, 1, NB), 256, SMEMSZ>>>(Wb1);
    // Branches 2/3: qkv projections on s2/s3
    tgemm_k<<<dim3(32, 2, NB), 256, SMEMSZ>>>(Wqkv2, hh, qk2, 64, 192, 0, (long)256 * HW, 128, (long)192 * HW, 0);
    tgemm_k<<<dim3(32, 2, NB), 256, SMEMSZ>>>(Wqkv3, hh, qk3, 64, 192, 0, (long)256 * HW, 192, (long)192 * HW, 0);
    softmax_k<<<2048, 256>>>(qk2, qk3);
    ctx_k<<<dim3(128, 2), 256>>>(qk2, qk3);
    ctxred_k<<<512, 256>>>();
    mproj_k<<<32, 256>>>(Wproj2, Wproj3);
    // attn output fused with proj: preB ch 128..191 / 192..255 = M[b] @ q[b]
    tgemm_k<<<dim3(32, 1, NB), 256, SMEMSZ>>>(Mm,                   qk2, preB, 64, 64, 4096, (long)192 * HW, 0, (long)256 * HW, 128);
    tgemm_k<<<dim3(32, 1, NB), 256, SMEMSZ>>>(Mm + (size_t)NB*4096, qk3, preB, 64, 64, 4096, (long)192 * HW, 0, (long)256 * HW, 192);

    // Branch BNs + ReLU
    stats_k<<<dim3(256, 8), 256>>>(preB, 256, 512);
    finalize_k<<<1, 64>>>(512, 64, gb0, bb0);
    finalize_k<<<1, 64>>>(576, 64, gb1, bb1);
    finalize_k<<<1, 64>>>(640, 64, ga2, ba2);
    finalize_k<<<1, 64>>>(704, 64, ga3, ba3);
    bnrelu_k<<<16384, 256>>>(preB, 512);

    // Final 256->256 conv, its BN, + shortcut BN + ReLU
    tgemm_k<<<dim3(32, 2, NB), 256, SMEMSZ>>>(W2, preB, pout, 256, 256, 0, (long)256 * HW, 0, (long)256 * HW, 0);
    stats_k<<<dim3(256, 8), 256>>>(pout, 256, 768);
    finalize_k<<<1, 256>>>(768, 256, g2, b2);
    final_k<<<16384, 256>>>((float*)d_out);
}

// round 4
// speedup vs baseline: 1.6168x; 1.3550x over previous
#include <cuda_runtime.h>
#include <cstdint>
#include <math.h>

#define HW 4096
#define NB 16
#define BK 32
#define NPART 2048

// ---------------- scratch (static device globals; no allocation) ----------------
static __device__ float g_tsc [(size_t)NB*256*HW];
static __device__ float g_h   [(size_t)NB*256*HW];   // stays PRE-BN; BN folded into consumers
static __device__ float g_qkv2[(size_t)NB*192*HW];
static __device__ float g_qkv3[(size_t)NB*192*HW];
static __device__ float g_preB[(size_t)NB*256*HW];   // PRE-BN branch outputs
static __device__ float g_pout[(size_t)NB*256*HW];
static __device__ float g_ctxp[2*NB*8*4096];
static __device__ float g_ctx [2*NB*4096];
static __device__ float g_Mm  [2*NB*4096];
static __device__ float g_psum  [(size_t)1024*NPART];
static __device__ float g_psumsq[(size_t)1024*NPART];
static __device__ float g_scale [1024];
static __device__ float g_shift [1024];

__device__ __forceinline__ uint32_t to_tf32(float x) {
    uint32_t y; asm("cvt.rna.tf32.f32 %0, %1;" : "=r"(y) : "f"(x)); return y;
}
__device__ __forceinline__ void mma8(float* c, const uint32_t* a, const uint32_t* b) {
    asm volatile("mma.sync.aligned.m16n8k8.row.col.f32.tf32.tf32.f32 "
        "{%0,%1,%2,%3}, {%4,%5,%6,%7}, {%8,%9}, {%0,%1,%2,%3};"
        : "+f"(c[0]), "+f"(c[1]), "+f"(c[2]), "+f"(c[3])
        : "r"(a[0]), "r"(a[1]), "r"(a[2]), "r"(a[3]), "r"(b[0]), "r"(b[1]));
}

// single-buffer smem (floats): A[128][36], B[32][132]
#define AS_OFF 0
#define BS_OFF 4608
#define SMEMSZ ((4608 + 4224) * 4)

// ---------------- tf32 mma.sync batched GEMM with fused BN-in / stats-out ----------------
// C[b] = W(b) @ bnrelu?(A[b]); per-channel partial sums of C into g_psum.
// grid: (32, ceil(M/128), NB), 256 threads, 2 blocks/SM.
__global__ __launch_bounds__(256, 2) void tgemm_k(
    const float* __restrict__ Wg, const float* __restrict__ A, float* __restrict__ C,
    int K, int Mrows, long wbs, long abs_, int acoff, long cbs, int ccoff,
    int bnslot, int statslot)
{
    extern __shared__ float sm[];
    const int b = blockIdx.z;
    const float* Wp = Wg + (size_t)b * wbs;
    const float* Ap = A + (size_t)b * abs_ + (size_t)acoff * HW;
    float* Cp = C + (size_t)b * cbs + (size_t)ccoff * HW;
    const int n0 = blockIdx.x * 128, m0 = blockIdx.y * 128;
    const int tid = threadIdx.x, lane = tid & 31, wid = tid >> 5;
    const int wm0 = (wid >> 2) * 64, wn0 = (wid & 3) * 32;
    const int qr = lane >> 2, qc = lane & 3;

    const int fam = tid >> 1, fac = (tid & 1) * 16;
    const int fbk = tid >> 3, fbc = (tid & 7) * 16;
    const bool avalid = (m0 + fam) < Mrows;
    const int nk = K / BK;

    float acc[4][4][4];
#pragma unroll
    for (int i = 0; i < 4; i++)
#pragma unroll
        for (int j = 0; j < 4; j++)
#pragma unroll
            for (int e = 0; e < 4; e++) acc[i][j][e] = 0.f;

    for (int kc = 0; kc < nk; kc++) {
        // ---- fill smem (with optional BN+ReLU on B side) ----
        {
            const float* wr = Wp + (size_t)(m0 + fam) * K + kc * BK + fac;
            const float* br = Ap + (size_t)(kc * BK + fbk) * HW + n0 + fbc;
            float bsc = 1.f, bsh = 0.f;
            if (bnslot >= 0) {
                bsc = g_scale[bnslot + acoff + kc * BK + fbk];
                bsh = g_shift[bnslot + acoff + kc * BK + fbk];
            }
            uint32_t* das = (uint32_t*)(sm + AS_OFF) + fam * 36 + fac;
            uint32_t* dbs = (uint32_t*)(sm + BS_OFF) + fbk * 132 + fbc;
#pragma unroll
            for (int t = 0; t < 4; t++) {
                float4 pa = avalid ? *(const float4*)(wr + t * 4) : make_float4(0.f, 0.f, 0.f, 0.f);
                float4 pb = *(const float4*)(br + t * 4);
                if (bnslot >= 0) {
                    pb.x = fmaxf(pb.x * bsc + bsh, 0.f);
                    pb.y = fmaxf(pb.y * bsc + bsh, 0.f);
                    pb.z = fmaxf(pb.z * bsc + bsh, 0.f);
                    pb.w = fmaxf(pb.w * bsc + bsh, 0.f);
                }
                das[t*4+0] = to_tf32(pa.x); das[t*4+1] = to_tf32(pa.y);
                das[t*4+2] = to_tf32(pa.z); das[t*4+3] = to_tf32(pa.w);
                dbs[t*4+0] = to_tf32(pb.x); dbs[t*4+1] = to_tf32(pb.y);
                dbs[t*4+2] = to_tf32(pb.z); dbs[t*4+3] = to_tf32(pb.w);
            }
        }
        __syncthreads();
        // ---- MMA over chunk ----
        const uint32_t* as = (const uint32_t*)(sm + AS_OFF);
        const uint32_t* bs = (const uint32_t*)(sm + BS_OFF);
#pragma unroll
        for (int ks = 0; ks < 4; ks++) {
            uint32_t af[4][4], bf[4][2];
            const int kk = ks * 8 + qc;
#pragma unroll
            for (int mt = 0; mt < 4; mt++) {
                const uint32_t* ap = as + (wm0 + mt * 16 + qr) * 36 + kk;
                af[mt][0] = ap[0];
                af[mt][1] = ap[8 * 36];
                af[mt][2] = ap[4];
                af[mt][3] = ap[8 * 36 + 4];
            }
#pragma unroll
            for (int nt = 0; nt < 4; nt++) {
                const uint32_t* bp = bs + kk * 132 + wn0 + nt * 8 + qr;
                bf[nt][0] = bp[0];
                bf[nt][1] = bp[4 * 132];
            }
#pragma unroll
            for (int mt = 0; mt < 4; mt++)
#pragma unroll
                for (int nt = 0; nt < 4; nt++) mma8(acc[mt][nt], af[mt], bf[nt]);
        }
        __syncthreads();
    }

    // ---- epilogue: C stores + fused per-channel stats partials ----
    const int pidx = (b * 32 + blockIdx.x) * 4 + (wid & 3);
#pragma unroll
    for (int mt = 0; mt < 4; mt++) {
        const int m = m0 + wm0 + mt * 16 + qr;
#pragma unroll
        for (int nt = 0; nt < 4; nt++) {
            const int n = n0 + wn0 + nt * 8 + qc * 2;
            if (m < Mrows)
                *(float2*)(Cp + (size_t)m * HW + n) = make_float2(acc[mt][nt][0], acc[mt][nt][1]);
            if (m + 8 < Mrows)
                *(float2*)(Cp + (size_t)(m + 8) * HW + n) = make_float2(acc[mt][nt][2], acc[mt][nt][3]);
        }
        if (statslot >= 0) {
            float s0 = 0.f, q0 = 0.f, s1 = 0.f, q1 = 0.f;
#pragma unroll
            for (int nt = 0; nt < 4; nt++) {
                s0 += acc[mt][nt][0] + acc[mt][nt][1];
                q0 += acc[mt][nt][0] * acc[mt][nt][0] + acc[mt][nt][1] * acc[mt][nt][1];
                s1 += acc[mt][nt][2] + acc[mt][nt][3];
                q1 += acc[mt][nt][2] * acc[mt][nt][2] + acc[mt][nt][3] * acc[mt][nt][3];
            }
#pragma unroll
            for (int off = 1; off < 4; off <<= 1) {
                s0 += __shfl_xor_sync(0xffffffffu, s0, off);
                q0 += __shfl_xor_sync(0xffffffffu, q0, off);
                s1 += __shfl_xor_sync(0xffffffffu, s1, off);
                q1 += __shfl_xor_sync(0xffffffffu, q1, off);
            }
            if (qc == 0) {
                if (m < Mrows) {
                    g_psum  [(size_t)(statslot + ccoff + m) * NPART + pidx] = s0;
                    g_psumsq[(size_t)(statslot + ccoff + m) * NPART + pidx] = q0;
                }
                if (m + 8 < Mrows) {
                    g_psum  [(size_t)(statslot + ccoff + m + 8) * NPART + pidx] = s1;
                    g_psumsq[(size_t)(statslot + ccoff + m + 8) * NPART + pidx] = q1;
                }
            }
        }
    }
}

// ---------------- tf32 implicit-GEMM 3x3 conv on s1 (BN-in via g_scale[320..383], stats-out) ----------------
__global__ __launch_bounds__(256, 2) void tconv_k(const float* __restrict__ Wb1)
{
    extern __shared__ float sm[];
    const int b = blockIdx.z;
    const float* Ap = g_h + (size_t)b * 256 * HW + (size_t)64 * HW;
    float* Cp = g_preB + (size_t)b * 256 * HW + (size_t)64 * HW;
    const int n0 = blockIdx.x * 128;
    const int tid = threadIdx.x, lane = tid & 31, wid = tid >> 5;
    const int wm0 = (wid >> 2) * 64, wn0 = (wid & 3) * 32;
    const int qr = lane >> 2, qc = lane & 3;
    const int fam = tid >> 1, fac = (tid & 1) * 16;
    const int fbk = tid >> 3, fbc = (tid & 7) * 16;
    const int nk = 18;

    float acc[4][4][4];
#pragma unroll
    for (int i = 0; i < 4; i++)
#pragma unroll
        for (int j = 0; j < 4; j++)
#pragma unroll
            for (int e = 0; e < 4; e++) acc[i][j][e] = 0.f;

    for (int kc = 0; kc < nk; kc++) {
        const int tap = kc >> 1, half = kc & 1;
        const int dy = tap / 3 - 1, dx = tap % 3 - 1;
        {
            uint32_t* das = (uint32_t*)(sm + AS_OFF) + fam * 36 + fac;
            uint32_t* dbs = (uint32_t*)(sm + BS_OFF) + fbk * 132 + fbc;
            // A: weights
#pragma unroll
            for (int s = 0; s < 16; s++) {
                float v = 0.f;
                if (fam < 64) {
                    int ic = half * 32 + fac + s;
                    v = Wb1[(size_t)fam * 576 + (size_t)ic * 9 + tap];
                }
                das[s] = to_tf32(v);
            }
            // B: shifted plane, BN+ReLU on in-bounds values
            const int ic = half * 32 + fbk;
            const float* plane = Ap + (size_t)ic * HW;
            const float bsc = g_scale[256 + 64 + ic], bsh = g_shift[256 + 64 + ic];
#pragma unroll
            for (int s = 0; s < 16; s++) {
                int p = n0 + fbc + s;
                int y = (p >> 6) + dy, x = (p & 63) + dx;
                float v = 0.f;
                if ((unsigned)y < 64u && (unsigned)x < 64u)
                    v = fmaxf(plane[y * 64 + x] * bsc + bsh, 0.f);
                dbs[s] = to_tf32(v);
            }
        }
        __syncthreads();
        const uint32_t* as = (const uint32_t*)(sm + AS_OFF);
        const uint32_t* bs = (const uint32_t*)(sm + BS_OFF);
#pragma unroll
        for (int ks = 0; ks < 4; ks++) {
            uint32_t af[4][4], bf[4][2];
            const int kk = ks * 8 + qc;
#pragma unroll
            for (int mt = 0; mt < 4; mt++) {
                const uint32_t* ap = as + (wm0 + mt * 16 + qr) * 36 + kk;
                af[mt][0] = ap[0];
                af[mt][1] = ap[8 * 36];
                af[mt][2] = ap[4];
                af[mt][3] = ap[8 * 36 + 4];
            }
#pragma unroll
            for (int nt = 0; nt < 4; nt++) {
                const uint32_t* bp = bs + kk * 132 + wn0 + nt * 8 + qr;
                bf[nt][0] = bp[0];
                bf[nt][1] = bp[4 * 132];
            }
#pragma unroll
            for (int mt = 0; mt < 4; mt++)
#pragma unroll
                for (int nt = 0; nt < 4; nt++) mma8(acc[mt][nt], af[mt], bf[nt]);
        }
        __syncthreads();
    }

    const int pidx = (b * 32 + blockIdx.x) * 4 + (wid & 3);
#pragma unroll
    for (int mt = 0; mt < 4; mt++) {
        const int m = wm0 + mt * 16 + qr;
#pragma unroll
        for (int nt = 0; nt < 4; nt++) {
            const int n = n0 + wn0 + nt * 8 + qc * 2;
            if (m < 64)
                *(float2*)(Cp + (size_t)m * HW + n) = make_float2(acc[mt][nt][0], acc[mt][nt][1]);
            if (m + 8 < 64)
                *(float2*)(Cp + (size_t)(m + 8) * HW + n) = make_float2(acc[mt][nt][2], acc[mt][nt][3]);
        }
        float s0 = 0.f, q0 = 0.f, s1 = 0.f, q1 = 0.f;
#pragma unroll
        for (int nt = 0; nt < 4; nt++) {
            s0 += acc[mt][nt][0] + acc[mt][nt][1];
            q0 += acc[mt][nt][0] * acc[mt][nt][0] + acc[mt][nt][1] * acc[mt][nt][1];
            s1 += acc[mt][nt][2] + acc[mt][nt][3];
            q1 += acc[mt][nt][2] * acc[mt][nt][2] + acc[mt][nt][3] * acc[mt][nt][3];
        }
#pragma unroll
        for (int off = 1; off < 4; off <<= 1) {
            s0 += __shfl_xor_sync(0xffffffffu, s0, off);
            q0 += __shfl_xor_sync(0xffffffffu, q0, off);
            s1 += __shfl_xor_sync(0xffffffffu, s1, off);
            q1 += __shfl_xor_sync(0xffffffffu, q1, off);
        }
        if (qc == 0) {
            if (m < 64) {
                g_psum  [(size_t)(512 + 64 + m) * NPART + pidx] = s0;
                g_psumsq[(size_t)(512 + 64 + m) * NPART + pidx] = q0;
            }
            if (m + 8 < 64) {
                g_psum  [(size_t)(512 + 64 + m + 8) * NPART + pidx] = s1;
                g_psumsq[(size_t)(512 + 64 + m + 8) * NPART + pidx] = q1;
            }
        }
    }
}

// ---------------- finalize: reduce NPART partials -> scale/shift ----------------
__global__ __launch_bounds__(256) void finalize_k(int slot, const float* __restrict__ gamma, const float* __restrict__ beta)
{
    const int c = blockIdx.x, tid = threadIdx.x;
    const float* ps = g_psum   + (size_t)(slot + c) * NPART;
    const float* pq = g_psumsq + (size_t)(slot + c) * NPART;
    float s = 0.f, q = 0.f;
    for (int i = tid; i < NPART; i += 256) { s += ps[i]; q += pq[i]; }
    __shared__ float ss[256], sq[256];
    ss[tid] = s; sq[tid] = q; __syncthreads();
    for (int st = 128; st > 0; st >>= 1) {
        if (tid < st) { ss[tid] += ss[tid + st]; sq[tid] += sq[tid + st]; }
        __syncthreads();
    }
    if (tid == 0) {
        const float inv = 1.f / 65536.f;
        float m = ss[0] * inv;
        float v = sq[0] * inv - m * m;
        float sc = gamma[c] * rsqrtf(v + 1e-5f);
        g_scale[slot + c] = sc;
        g_shift[slot + c] = beta[c] - m * sc;
    }
}

// ---------------- softmax over N=4096 on the k-section of qkv ----------------
__global__ __launch_bounds__(256) void softmax_k(float* __restrict__ q2, float* __restrict__ q3)
{
    __shared__ float row[4096];
    __shared__ float red[256];
    const int id = blockIdx.x;
    const int lga = id >> 10, rem = id & 1023;
    const int b = rem >> 6, c = rem & 63;
    float* p = (lga ? q3 : q2) + ((size_t)b * 192 + 64 + c) * HW;
    const int tid = threadIdx.x;

    float m = -1e30f;
    for (int i = tid; i < 4096; i += 256) { float v = p[i]; row[i] = v; m = fmaxf(m, v); }
    red[tid] = m; __syncthreads();
    for (int st = 128; st > 0; st >>= 1) { if (tid < st) red[tid] = fmaxf(red[tid], red[tid + st]); __syncthreads(); }
    m = red[0]; __syncthreads();

    float s = 0.f;
    for (int i = tid; i < 4096; i += 256) { float e = expf(row[i] - m); row[i] = e; s += e; }
    red[tid] = s; __syncthreads();
    for (int st = 128; st > 0; st >>= 1) { if (tid < st) red[tid] += red[tid + st]; __syncthreads(); }
    float inv = 1.f / red[0];
    for (int i = tid; i < 4096; i += 256) p[i] = row[i] * inv;
}

// ---------------- ctx partials: ctx[b,c,d] = sum_n k[c,n]*v[d,n] ----------------
__global__ __launch_bounds__(256) void ctx_k(const float* __restrict__ q2, const float* __restrict__ q3)
{
    __shared__ float Ks[64][33];
    __shared__ float Vs[64][33];
    const int chunk = blockIdx.x >> 4, b = blockIdx.x & 15, lga = blockIdx.y;
    const float* base = (lga ? q3 : q2) + (size_t)b * 192 * HW;
    const float* kp = base + (size_t)64 * HW;
    const float* vp = base + (size_t)128 * HW;
    const int tid = threadIdx.x;
    const int cb = (tid >> 4) << 2, db = (tid & 15) << 2;

    float acc[4][4];
#pragma unroll
    for (int i = 0; i < 4; i++)
#pragma unroll
        for (int j = 0; j < 4; j++) acc[i][j] = 0.f;

    for (int sub = 0; sub < 16; sub++) {
        const int n0 = chunk * 512 + sub * 32;
        for (int idx = tid; idx < 2048; idx += 256) {
            int r = idx >> 5, cc = idx & 31;
            Ks[r][cc] = kp[(size_t)r * HW + n0 + cc];
            Vs[r][cc] = vp[(size_t)r * HW + n0 + cc];
        }
        __syncthreads();
#pragma unroll 8
        for (int nn = 0; nn < 32; nn++) {
            float kc[4], vd[4];
#pragma unroll
            for (int i = 0; i < 4; i++) { kc[i] = Ks[cb + i][nn]; vd[i] = Vs[db + i][nn]; }
#pragma unroll
            for (int i = 0; i < 4; i++)
#pragma unroll
                for (int j = 0; j < 4; j++) acc[i][j] += kc[i] * vd[j];
        }
        __syncthreads();
    }
    float* cp = g_ctxp + ((size_t)(lga * 16 + b) * 8 + chunk) * 4096;
#pragma unroll
    for (int i = 0; i < 4; i++)
#pragma unroll
        for (int j = 0; j < 4; j++) cp[(cb + i) * 64 + db + j] = acc[i][j];
}

__global__ void ctxred_k()
{
    int i = blockIdx.x * 256 + threadIdx.x;
    if (i >= 2 * NB * 4096) return;
    int pair = i >> 12, e = i & 4095;
    const float* cp = g_ctxp + (size_t)pair * 8 * 4096 + e;
    float s = 0.f;
#pragma unroll
    for (int p = 0; p < 8; p++) s += cp[p * 4096];
    g_ctx[i] = s;
}

// ---------------- M[o,c] = sum_d Wproj[o,d] * ctx[c,d] ----------------
__global__ __launch_bounds__(256) void mproj_k(const float* __restrict__ Wp2, const float* __restrict__ Wp3)
{
    const int id = blockIdx.x;
    const int lga = id >> 4;
    const float* Wp = lga ? Wp3 : Wp2;
    const float* cx = g_ctx + (size_t)id * 4096;
    float* Mo = g_Mm + (size_t)id * 4096;
    for (int e = threadIdx.x; e < 4096; e += 256) {
        int o = e >> 6, c = e & 63;
        float s = 0.f;
#pragma unroll 16
        for (int d = 0; d < 64; d++) s += Wp[o * 64 + d] * cx[c * 64 + d];
        Mo[o * 64 + c] = s;
    }
}

// ---------------- final: out = relu( bn2(pout) + bn_sc(tsc) ) ----------------
__global__ __launch_bounds__(256) void final_k(float* __restrict__ out)
{
    size_t i = (size_t)blockIdx.x * 256 + threadIdx.x;
    int c = (int)((i >> 10) & 255);
    float s2 = g_scale[768 + c], h2 = g_shift[768 + c];
    float s0 = g_scale[c],       h0 = g_shift[c];
    float4 p = ((const float4*)g_pout)[i];
    float4 r = ((const float4*)g_tsc)[i];
    p.x = fmaxf(p.x * s2 + h2 + r.x * s0 + h0, 0.f);
    p.y = fmaxf(p.y * s2 + h2 + r.y * s0 + h0, 0.f);
    p.z = fmaxf(p.z * s2 + h2 + r.z * s0 + h0, 0.f);
    p.w = fmaxf(p.w * s2 + h2 + r.w * s0 + h0, 0.f);
    ((float4*)out)[i] = p;
}

// ---------------- launch ----------------
extern "C" void kernel_launch(void* const* d_in, const int* in_sizes, int n_in,
                              void* d_out, int out_size)
{
    (void)in_sizes; (void)n_in; (void)out_size;
    const float* x      = (const float*)d_in[0];
    const float* W_sc   = (const float*)d_in[1];
    const float* gsc    = (const float*)d_in[2];
    const float* bsc    = (const float*)d_in[3];
    const float* W1     = (const float*)d_in[4];
    const float* g1     = (const float*)d_in[5];
    const float* b1     = (const float*)d_in[6];
    const float* Wb0    = (const float*)d_in[7];
    const float* gb0    = (const float*)d_in[8];
    const float* bb0    = (const float*)d_in[9];
    const float* Wb1    = (const float*)d_in[10];
    const float* gb1    = (const float*)d_in[11];
    const float* bb1    = (const float*)d_in[12];
    const float* Wqkv2  = (const float*)d_in[13];
    const float* Wproj2 = (const float*)d_in[14];
    const float* ga2    = (const float*)d_in[15];
    const float* ba2    = (const float*)d_in[16];
    const float* Wqkv3  = (const float*)d_in[17];
    const float* Wproj3 = (const float*)d_in[18];
    const float* ga3    = (const float*)d_in[19];
    const float* ba3    = (const float*)d_in[20];
    const float* W2     = (const float*)d_in[21];
    const float* g2     = (const float*)d_in[22];
    const float* b2     = (const float*)d_in[23];

    float *tsc, *hh, *qk2, *qk3, *preB, *pout, *Mm;
    cudaGetSymbolAddress((void**)&tsc,  g_tsc);
    cudaGetSymbolAddress((void**)&hh,   g_h);
    cudaGetSymbolAddress((void**)&qk2,  g_qkv2);
    cudaGetSymbolAddress((void**)&qk3,  g_qkv3);
    cudaGetSymbolAddress((void**)&preB, g_preB);
    cudaGetSymbolAddress((void**)&pout, g_pout);
    cudaGetSymbolAddress((void**)&Mm,   g_Mm);

    // Stage 1: two 128->256 convs over x; stats fused into epilogues
    tgemm_k<<<dim3(32, 2, NB), 256, SMEMSZ>>>(W_sc, x, tsc, 128, 256, 0, (long)128 * HW, 0, (long)256 * HW, 0, -1, 0);
    tgemm_k<<<dim3(32, 2, NB), 256, SMEMSZ>>>(W1,   x, hh,  128, 256, 0, (long)128 * HW, 0, (long)256 * HW, 0, -1, 256);
    finalize_k<<<256, 256>>>(0,   gsc, bsc);
    finalize_k<<<256, 256>>>(256, g1,  b1);

    // Branch 0: 1x1 conv on s0 (BN of h folded into B loader)
    tgemm_k<<<dim3(32, 1, NB), 256, SMEMSZ>>>(Wb0, hh, preB, 64, 64, 0, (long)256 * HW, 0, (long)256 * HW, 0, 256, 512);
    // Branch 1: 3x3 conv on s1 (implicit GEMM, BN folded)
    tconv_k<<<dim3(32, 1, NB), 256, SMEMSZ>>>(Wb1);
    // Branches 2/3: qkv projections (BN folded; no stats)
    tgemm_k<<<dim3(32, 2, NB), 256, SMEMSZ>>>(Wqkv2, hh, qk2, 64, 192, 0, (long)256 * HW, 128, (long)192 * HW, 0, 256, -1);
    tgemm_k<<<dim3(32, 2, NB), 256, SMEMSZ>>>(Wqkv3, hh, qk3, 64, 192, 0, (long)256 * HW, 192, (long)192 * HW, 0, 256, -1);
    softmax_k<<<2048, 256>>>(qk2, qk3);
    ctx_k<<<dim3(128, 2), 256>>>(qk2, qk3);
    ctxred_k<<<512, 256>>>();
    mproj_k<<<32, 256>>>(Wproj2, Wproj3);
    // attn output fused with proj: preB ch 128..191 / 192..255 = M[b] @ q[b]
    tgemm_k<<<dim3(32, 1, NB), 256, SMEMSZ>>>(Mm,                   qk2, preB, 64, 64, 4096, (long)192 * HW, 0, (long)256 * HW, 128, -1, 512);
    tgemm_k<<<dim3(32, 1, NB), 256, SMEMSZ>>>(Mm + (size_t)NB*4096, qk3, preB, 64, 64, 4096, (long)192 * HW, 0, (long)256 * HW, 192, -1, 512);

    // Branch BN params
    finalize_k<<<64, 256>>>(512, gb0, bb0);
    finalize_k<<<64, 256>>>(576, gb1, bb1);
    finalize_k<<<64, 256>>>(640, ga2, ba2);
    finalize_k<<<64, 256>>>(704, ga3, ba3);

    // Final 256->256 conv (BN of preB folded into B loader; stats fused)
    tgemm_k<<<dim3(32, 2, NB), 256, SMEMSZ>>>(W2, preB, pout, 256, 256, 0, (long)256 * HW, 0, (long)256 * HW, 0, 512, 768);
    finalize_k<<<256, 256>>>(768, g2, b2);
    final_k<<<16384, 256>>>((float*)d_out);
}

// round 5
// speedup vs baseline: 1.9765x; 1.2225x over previous
#include <cuda_runtime.h>
#include <cstdint>
#include <math.h>

#define HW 4096
#define NB 16
#define BK 32
#define NPART 2048

// ---------------- scratch (static device globals; no allocation) ----------------
static __device__ float g_tsc [(size_t)NB*256*HW];
static __device__ float g_h   [(size_t)NB*256*HW];   // PRE-BN; BN folded into consumers
static __device__ float g_qkv2[(size_t)NB*192*HW];
static __device__ float g_qkv3[(size_t)NB*192*HW];
static __device__ float g_preB[(size_t)NB*256*HW];   // PRE-BN branch outputs
static __device__ float g_pout[(size_t)NB*256*HW];
static __device__ float g_ctxp[2*NB*8*4096];
static __device__ float g_ctx [2*NB*4096];
static __device__ float g_Mm  [2*NB*4096];
static __device__ float g_psum  [(size_t)1024*NPART];
static __device__ float g_psumsq[(size_t)1024*NPART];
static __device__ float g_scale [1024];
static __device__ float g_shift [1024];

__device__ __forceinline__ uint32_t to_tf32(float x) {
    uint32_t y; asm("cvt.rna.tf32.f32 %0, %1;" : "=r"(y) : "f"(x)); return y;
}
__device__ __forceinline__ uint4 cvt4(float4 v) {
    uint4 o; o.x = to_tf32(v.x); o.y = to_tf32(v.y); o.z = to_tf32(v.z); o.w = to_tf32(v.w);
    return o;
}
__device__ __forceinline__ void mma8(float* c, const uint32_t* a, const uint32_t* b) {
    asm volatile("mma.sync.aligned.m16n8k8.row.col.f32.tf32.tf32.f32 "
        "{%0,%1,%2,%3}, {%4,%5,%6,%7}, {%8,%9}, {%0,%1,%2,%3};"
        : "+f"(c[0]), "+f"(c[1]), "+f"(c[2]), "+f"(c[3])
        : "r"(a[0]), "r"(a[1]), "r"(a[2]), "r"(a[3]), "r"(b[0]), "r"(b[1]));
}

// smem (floats): A[128][36] (or 64 rows), B[32][132]
#define AS_OFF 0
#define BS128_OFF 4608
#define SMEMSZ128 ((4608 + 4224) * 4)
#define BS64_OFF 2304
#define SMEMSZ64 ((2304 + 4224) * 4)

// ================= 128-row tile GEMM (M multiple of 128) =================
__global__ __launch_bounds__(256, 2) void tgemm_k(
    const float* __restrict__ Wg, const float* __restrict__ A, float* __restrict__ C,
    int K, long wbs, long abs_, int acoff, long cbs, int ccoff,
    int bnslot, int statslot)
{
    extern __shared__ float sm[];
    const int b = blockIdx.z;
    const float* Wp = Wg + (size_t)b * wbs;
    const float* Ap = A + (size_t)b * abs_ + (size_t)acoff * HW;
    float* Cp = C + (size_t)b * cbs + (size_t)ccoff * HW;
    const int n0 = blockIdx.x * 128, m0 = blockIdx.y * 128;
    const int tid = threadIdx.x, lane = tid & 31, wid = tid >> 5;
    const int wm0 = (wid >> 2) * 64, wn0 = (wid & 3) * 32;
    const int qr = lane >> 2, qc = lane & 3;

    const int fam = tid >> 1, fac = (tid & 1) * 16;
    const int fbk = tid >> 3, fbc = (tid & 7) * 16;
    const int rot = (tid & 7) >> 1;
    const int nk = K / BK;

    float acc[4][4][4];
#pragma unroll
    for (int i = 0; i < 4; i++)
#pragma unroll
        for (int j = 0; j < 4; j++)
#pragma unroll
            for (int e = 0; e < 4; e++) acc[i][j][e] = 0.f;

    for (int kc = 0; kc < nk; kc++) {
        {
            const float* wr = Wp + (size_t)(m0 + fam) * K + kc * BK + fac;
            const float* br = Ap + (size_t)(kc * BK + fbk) * HW + n0 + fbc;
            float bsc = 1.f, bsh = 0.f;
            if (bnslot >= 0) {
                bsc = g_scale[bnslot + acoff + kc * BK + fbk];
                bsh = g_shift[bnslot + acoff + kc * BK + fbk];
            }
            uint32_t* das = (uint32_t*)(sm + AS_OFF) + fam * 36 + fac;
            uint32_t* dbs = (uint32_t*)(sm + BS128_OFF) + fbk * 132 + fbc;
#pragma unroll
            for (int t = 0; t < 4; t++)
                *(uint4*)(das + t * 4) = cvt4(*(const float4*)(wr + t * 4));
#pragma unroll
            for (int j = 0; j < 4; j++) {
                const int t = (j + rot) & 3;
                float4 pb = *(const float4*)(br + t * 4);
                if (bnslot >= 0) {
                    pb.x = fmaxf(pb.x * bsc + bsh, 0.f);
                    pb.y = fmaxf(pb.y * bsc + bsh, 0.f);
                    pb.z = fmaxf(pb.z * bsc + bsh, 0.f);
                    pb.w = fmaxf(pb.w * bsc + bsh, 0.f);
                }
                *(uint4*)(dbs + t * 4) = cvt4(pb);
            }
        }
        __syncthreads();
        const uint32_t* as = (const uint32_t*)(sm + AS_OFF);
        const uint32_t* bs = (const uint32_t*)(sm + BS128_OFF);
#pragma unroll
        for (int ks = 0; ks < 4; ks++) {
            uint32_t af[4][4], bf[4][2];
            const int kk = ks * 8 + qc;
#pragma unroll
            for (int mt = 0; mt < 4; mt++) {
                const uint32_t* ap = as + (wm0 + mt * 16 + qr) * 36 + kk;
                af[mt][0] = ap[0];
                af[mt][1] = ap[8 * 36];
                af[mt][2] = ap[4];
                af[mt][3] = ap[8 * 36 + 4];
            }
#pragma unroll
            for (int nt = 0; nt < 4; nt++) {
                const uint32_t* bp = bs + kk * 132 + wn0 + nt * 8 + qr;
                bf[nt][0] = bp[0];
                bf[nt][1] = bp[4 * 132];
            }
#pragma unroll
            for (int mt = 0; mt < 4; mt++)
#pragma unroll
                for (int nt = 0; nt < 4; nt++) mma8(acc[mt][nt], af[mt], bf[nt]);
        }
        __syncthreads();
    }

    const int pidx = (b * 32 + blockIdx.x) * 4 + (wid & 3);
#pragma unroll
    for (int mt = 0; mt < 4; mt++) {
        const int m = m0 + wm0 + mt * 16 + qr;
#pragma unroll
        for (int nt = 0; nt < 4; nt++) {
            const int n = n0 + wn0 + nt * 8 + qc * 2;
            *(float2*)(Cp + (size_t)m * HW + n) = make_float2(acc[mt][nt][0], acc[mt][nt][1]);
            *(float2*)(Cp + (size_t)(m + 8) * HW + n) = make_float2(acc[mt][nt][2], acc[mt][nt][3]);
        }
        if (statslot >= 0) {
            float s0 = 0.f, q0 = 0.f, s1 = 0.f, q1 = 0.f;
#pragma unroll
            for (int nt = 0; nt < 4; nt++) {
                s0 += acc[mt][nt][0] + acc[mt][nt][1];
                q0 += acc[mt][nt][0] * acc[mt][nt][0] + acc[mt][nt][1] * acc[mt][nt][1];
                s1 += acc[mt][nt][2] + acc[mt][nt][3];
                q1 += acc[mt][nt][2] * acc[mt][nt][2] + acc[mt][nt][3] * acc[mt][nt][3];
            }
#pragma unroll
            for (int off = 1; off < 4; off <<= 1) {
                s0 += __shfl_xor_sync(0xffffffffu, s0, off);
                q0 += __shfl_xor_sync(0xffffffffu, q0, off);
                s1 += __shfl_xor_sync(0xffffffffu, s1, off);
                q1 += __shfl_xor_sync(0xffffffffu, q1, off);
            }
            if (qc == 0) {
                g_psum  [(size_t)(statslot + ccoff + m) * NPART + pidx] = s0;
                g_psumsq[(size_t)(statslot + ccoff + m) * NPART + pidx] = q0;
                g_psum  [(size_t)(statslot + ccoff + m + 8) * NPART + pidx] = s1;
                g_psumsq[(size_t)(statslot + ccoff + m + 8) * NPART + pidx] = q1;
            }
        }
    }
}

// ================= 64-row tile GEMM (Mrows <= blockIdx.y*64+64, exact) =================
__global__ __launch_bounds__(256, 2) void tgemm64_k(
    const float* __restrict__ Wg, const float* __restrict__ A, float* __restrict__ C,
    int K, long wbs, long abs_, int acoff, long cbs, int ccoff,
    int bnslot, int statslot)
{
    extern __shared__ float sm[];
    const int b = blockIdx.z;
    const float* Wp = Wg + (size_t)b * wbs;
    const float* Ap = A + (size_t)b * abs_ + (size_t)acoff * HW;
    float* Cp = C + (size_t)b * cbs + (size_t)ccoff * HW;
    const int n0 = blockIdx.x * 128, m0 = blockIdx.y * 64;
    const int tid = threadIdx.x, lane = tid & 31, wid = tid >> 5;
    const int wm0 = (wid >> 2) * 32, wn0 = (wid & 3) * 32;
    const int qr = lane >> 2, qc = lane & 3;

    const int fam = tid >> 2, fac = (tid & 3) * 8;          // A: 64 rows x 32 cols, 8 floats/thread
    const int fbk = tid >> 3, fbc = (tid & 7) * 16;
    const int rot = (tid & 7) >> 1;
    const int nk = K / BK;

    float acc[2][4][4];
#pragma unroll
    for (int i = 0; i < 2; i++)
#pragma unroll
        for (int j = 0; j < 4; j++)
#pragma unroll
            for (int e = 0; e < 4; e++) acc[i][j][e] = 0.f;

    for (int kc = 0; kc < nk; kc++) {
        {
            const float* wr = Wp + (size_t)(m0 + fam) * K + kc * BK + fac;
            const float* br = Ap + (size_t)(kc * BK + fbk) * HW + n0 + fbc;
            float bsc = 1.f, bsh = 0.f;
            if (bnslot >= 0) {
                bsc = g_scale[bnslot + acoff + kc * BK + fbk];
                bsh = g_shift[bnslot + acoff + kc * BK + fbk];
            }
            uint32_t* das = (uint32_t*)(sm + AS_OFF) + fam * 36 + fac;
            uint32_t* dbs = (uint32_t*)(sm + BS64_OFF) + fbk * 132 + fbc;
#pragma unroll
            for (int t = 0; t < 2; t++)
                *(uint4*)(das + t * 4) = cvt4(*(const float4*)(wr + t * 4));
#pragma unroll
            for (int j = 0; j < 4; j++) {
                const int t = (j + rot) & 3;
                float4 pb = *(const float4*)(br + t * 4);
                if (bnslot >= 0) {
                    pb.x = fmaxf(pb.x * bsc + bsh, 0.f);
                    pb.y = fmaxf(pb.y * bsc + bsh, 0.f);
                    pb.z = fmaxf(pb.z * bsc + bsh, 0.f);
                    pb.w = fmaxf(pb.w * bsc + bsh, 0.f);
                }
                *(uint4*)(dbs + t * 4) = cvt4(pb);
            }
        }
        __syncthreads();
        const uint32_t* as = (const uint32_t*)(sm + AS_OFF);
        const uint32_t* bs = (const uint32_t*)(sm + BS64_OFF);
#pragma unroll
        for (int ks = 0; ks < 4; ks++) {
            uint32_t af[2][4], bf[4][2];
            const int kk = ks * 8 + qc;
#pragma unroll
            for (int mt = 0; mt < 2; mt++) {
                const uint32_t* ap = as + (wm0 + mt * 16 + qr) * 36 + kk;
                af[mt][0] = ap[0];
                af[mt][1] = ap[8 * 36];
                af[mt][2] = ap[4];
                af[mt][3] = ap[8 * 36 + 4];
            }
#pragma unroll
            for (int nt = 0; nt < 4; nt++) {
                const uint32_t* bp = bs + kk * 132 + wn0 + nt * 8 + qr;
                bf[nt][0] = bp[0];
                bf[nt][1] = bp[4 * 132];
            }
#pragma unroll
            for (int mt = 0; mt < 2; mt++)
#pragma unroll
                for (int nt = 0; nt < 4; nt++) mma8(acc[mt][nt], af[mt], bf[nt]);
        }
        __syncthreads();
    }

    const int pidx = (b * 32 + blockIdx.x) * 4 + (wid & 3);
#pragma unroll
    for (int mt = 0; mt < 2; mt++) {
        const int m = m0 + wm0 + mt * 16 + qr;
#pragma unroll
        for (int nt = 0; nt < 4; nt++) {
            const int n = n0 + wn0 + nt * 8 + qc * 2;
            *(float2*)(Cp + (size_t)m * HW + n) = make_float2(acc[mt][nt][0], acc[mt][nt][1]);
            *(float2*)(Cp + (size_t)(m + 8) * HW + n) = make_float2(acc[mt][nt][2], acc[mt][nt][3]);
        }
        if (statslot >= 0) {
            float s0 = 0.f, q0 = 0.f, s1 = 0.f, q1 = 0.f;
#pragma unroll
            for (int nt = 0; nt < 4; nt++) {
                s0 += acc[mt][nt][0] + acc[mt][nt][1];
                q0 += acc[mt][nt][0] * acc[mt][nt][0] + acc[mt][nt][1] * acc[mt][nt][1];
                s1 += acc[mt][nt][2] + acc[mt][nt][3];
                q1 += acc[mt][nt][2] * acc[mt][nt][2] + acc[mt][nt][3] * acc[mt][nt][3];
            }
#pragma unroll
            for (int off = 1; off < 4; off <<= 1) {
                s0 += __shfl_xor_sync(0xffffffffu, s0, off);
                q0 += __shfl_xor_sync(0xffffffffu, q0, off);
                s1 += __shfl_xor_sync(0xffffffffu, s1, off);
                q1 += __shfl_xor_sync(0xffffffffu, q1, off);
            }
            if (qc == 0) {
                g_psum  [(size_t)(statslot + ccoff + m) * NPART + pidx] = s0;
                g_psumsq[(size_t)(statslot + ccoff + m) * NPART + pidx] = q0;
                g_psum  [(size_t)(statslot + ccoff + m + 8) * NPART + pidx] = s1;
                g_psumsq[(size_t)(statslot + ccoff + m + 8) * NPART + pidx] = q1;
            }
        }
    }
}

// ================= 64-row implicit-GEMM 3x3 conv on s1 (BN-in, stats-out) =================
__global__ __launch_bounds__(256, 2) void tconv_k(const float* __restrict__ Wb1)
{
    extern __shared__ float sm[];
    const int b = blockIdx.z;
    const float* Ap = g_h + (size_t)b * 256 * HW + (size_t)64 * HW;
    float* Cp = g_preB + (size_t)b * 256 * HW + (size_t)64 * HW;
    const int n0 = blockIdx.x * 128;
    const int tid = threadIdx.x, lane = tid & 31, wid = tid >> 5;
    const int wm0 = (wid >> 2) * 32, wn0 = (wid & 3) * 32;
    const int qr = lane >> 2, qc = lane & 3;
    const int fam = tid >> 2, fac = (tid & 3) * 8;
    const int fbk = tid >> 3, fbc = (tid & 7) * 16;
    const int rot = (tid & 7) >> 1;
    const int nk = 18;

    float acc[2][4][4];
#pragma unroll
    for (int i = 0; i < 2; i++)
#pragma unroll
        for (int j = 0; j < 4; j++)
#pragma unroll
            for (int e = 0; e < 4; e++) acc[i][j][e] = 0.f;

    for (int kc = 0; kc < nk; kc++) {
        const int tap = kc >> 1, half = kc & 1;
        const int dy = tap / 3 - 1, dx = tap % 3 - 1;
        {
            uint32_t* das = (uint32_t*)(sm + AS_OFF) + fam * 36 + fac;
            uint32_t* dbs = (uint32_t*)(sm + BS64_OFF) + fbk * 132 + fbc;
            const float* wr = Wb1 + (size_t)fam * 576 + tap;
#pragma unroll
            for (int t = 0; t < 2; t++) {
                float4 v;
                int ic = half * 32 + fac + t * 4;
                v.x = wr[(ic + 0) * 9]; v.y = wr[(ic + 1) * 9];
                v.z = wr[(ic + 2) * 9]; v.w = wr[(ic + 3) * 9];
                *(uint4*)(das + t * 4) = cvt4(v);
            }
            const int ic = half * 32 + fbk;
            const float* plane = Ap + (size_t)ic * HW;
            const float bsc = g_scale[256 + 64 + ic], bsh = g_shift[256 + 64 + ic];
#pragma unroll
            for (int j = 0; j < 4; j++) {
                const int t = (j + rot) & 3;
                float4 v;
                float* ve = (float*)&v;
#pragma unroll
                for (int e = 0; e < 4; e++) {
                    int p = n0 + fbc + t * 4 + e;
                    int y = (p >> 6) + dy, x = (p & 63) + dx;
                    float u = 0.f;
                    if ((unsigned)y < 64u && (unsigned)x < 64u)
                        u = fmaxf(plane[y * 64 + x] * bsc + bsh, 0.f);
                    ve[e] = u;
                }
                *(uint4*)(dbs + t * 4) = cvt4(v);
            }
        }
        __syncthreads();
        const uint32_t* as = (const uint32_t*)(sm + AS_OFF);
        const uint32_t* bs = (const uint32_t*)(sm + BS64_OFF);
#pragma unroll
        for (int ks = 0; ks < 4; ks++) {
            uint32_t af[2][4], bf[4][2];
            const int kk = ks * 8 + qc;
#pragma unroll
            for (int mt = 0; mt < 2; mt++) {
                const uint32_t* ap = as + (wm0 + mt * 16 + qr) * 36 + kk;
                af[mt][0] = ap[0];
                af[mt][1] = ap[8 * 36];
                af[mt][2] = ap[4];
                af[mt][3] = ap[8 * 36 + 4];
            }
#pragma unroll
            for (int nt = 0; nt < 4; nt++) {
                const uint32_t* bp = bs + kk * 132 + wn0 + nt * 8 + qr;
                bf[nt][0] = bp[0];
                bf[nt][1] = bp[4 * 132];
            }
#pragma unroll
            for (int mt = 0; mt < 2; mt++)
#pragma unroll
                for (int nt = 0; nt < 4; nt++) mma8(acc[mt][nt], af[mt], bf[nt]);
        }
        __syncthreads();
    }

    const int pidx = (b * 32 + blockIdx.x) * 4 + (wid & 3);
#pragma unroll
    for (int mt = 0; mt < 2; mt++) {
        const int m = wm0 + mt * 16 + qr;
#pragma unroll
        for (int nt = 0; nt < 4; nt++) {
            const int n = n0 + wn0 + nt * 8 + qc * 2;
            *(float2*)(Cp + (size_t)m * HW + n) = make_float2(acc[mt][nt][0], acc[mt][nt][1]);
            *(float2*)(Cp + (size_t)(m + 8) * HW + n) = make_float2(acc[mt][nt][2], acc[mt][nt][3]);
        }
        float s0 = 0.f, q0 = 0.f, s1 = 0.f, q1 = 0.f;
#pragma unroll
        for (int nt = 0; nt < 4; nt++) {
            s0 += acc[mt][nt][0] + acc[mt][nt][1];
            q0 += acc[mt][nt][0] * acc[mt][nt][0] + acc[mt][nt][1] * acc[mt][nt][1];
            s1 += acc[mt][nt][2] + acc[mt][nt][3];
            q1 += acc[mt][nt][2] * acc[mt][nt][2] + acc[mt][nt][3] * acc[mt][nt][3];
        }
#pragma unroll
        for (int off = 1; off < 4; off <<= 1) {
            s0 += __shfl_xor_sync(0xffffffffu, s0, off);
            q0 += __shfl_xor_sync(0xffffffffu, q0, off);
            s1 += __shfl_xor_sync(0xffffffffu, s1, off);
            q1 += __shfl_xor_sync(0xffffffffu, q1, off);
        }
        if (qc == 0) {
            g_psum  [(size_t)(576 + m) * NPART + pidx] = s0;
            g_psumsq[(size_t)(576 + m) * NPART + pidx] = q0;
            g_psum  [(size_t)(576 + m + 8) * NPART + pidx] = s1;
            g_psumsq[(size_t)(576 + m + 8) * NPART + pidx] = q1;
        }
    }
}

// ---------------- finalize: reduce NPART partials -> scale/shift ----------------
__global__ __launch_bounds__(256) void finalize_k(int slot, const float* __restrict__ gamma, const float* __restrict__ beta)
{
    const int c = blockIdx.x, tid = threadIdx.x;
    const float* ps = g_psum   + (size_t)(slot + c) * NPART;
    const float* pq = g_psumsq + (size_t)(slot + c) * NPART;
    float s = 0.f, q = 0.f;
    for (int i = tid; i < NPART; i += 256) { s += ps[i]; q += pq[i]; }
    __shared__ float ss[256], sq[256];
    ss[tid] = s; sq[tid] = q; __syncthreads();
    for (int st = 128; st > 0; st >>= 1) {
        if (tid < st) { ss[tid] += ss[tid + st]; sq[tid] += sq[tid + st]; }
        __syncthreads();
    }
    if (tid == 0) {
        const float inv = 1.f / 65536.f;
        float m = ss[0] * inv;
        float v = sq[0] * inv - m * m;
        float sc = gamma[c] * rsqrtf(v + 1e-5f);
        g_scale[slot + c] = sc;
        g_shift[slot + c] = beta[c] - m * sc;
    }
}

// ---------------- softmax over N=4096 on the k-section of qkv ----------------
__global__ __launch_bounds__(256) void softmax_k(float* __restrict__ q2, float* __restrict__ q3)
{
    __shared__ float row[4096];
    __shared__ float red[256];
    const int id = blockIdx.x;
    const int lga = id >> 10, rem = id & 1023;
    const int b = rem >> 6, c = rem & 63;
    float* p = (lga ? q3 : q2) + ((size_t)b * 192 + 64 + c) * HW;
    const int tid = threadIdx.x;

    float m = -1e30f;
    for (int i = tid; i < 4096; i += 256) { float v = p[i]; row[i] = v; m = fmaxf(m, v); }
    red[tid] = m; __syncthreads();
    for (int st = 128; st > 0; st >>= 1) { if (tid < st) red[tid] = fmaxf(red[tid], red[tid + st]); __syncthreads(); }
    m = red[0]; __syncthreads();

    float s = 0.f;
    for (int i = tid; i < 4096; i += 256) { float e = expf(row[i] - m); row[i] = e; s += e; }
    red[tid] = s; __syncthreads();
    for (int st = 128; st > 0; st >>= 1) { if (tid < st) red[tid] += red[tid + st]; __syncthreads(); }
    float inv = 1.f / red[0];
    for (int i = tid; i < 4096; i += 256) p[i] = row[i] * inv;
}

// ---------------- ctx partials: ctx[b,c,d] = sum_n k[c,n]*v[d,n] ----------------
__global__ __launch_bounds__(256) void ctx_k(const float* __restrict__ q2, const float* __restrict__ q3)
{
    __shared__ float Ks[64][33];
    __shared__ float Vs[64][33];
    const int chunk = blockIdx.x >> 4, b = blockIdx.x & 15, lga = blockIdx.y;
    const float* base = (lga ? q3 : q2) + (size_t)b * 192 * HW;
    const float* kp = base + (size_t)64 * HW;
    const float* vp = base + (size_t)128 * HW;
    const int tid = threadIdx.x;
    const int cb = (tid >> 4) << 2, db = (tid & 15) << 2;

    float acc[4][4];
#pragma unroll
    for (int i = 0; i < 4; i++)
#pragma unroll
        for (int j = 0; j < 4; j++) acc[i][j] = 0.f;

    for (int sub = 0; sub < 16; sub++) {
        const int n0 = chunk * 512 + sub * 32;
        for (int idx = tid; idx < 2048; idx += 256) {
            int r = idx >> 5, cc = idx & 31;
            Ks[r][cc] = kp[(size_t)r * HW + n0 + cc];
            Vs[r][cc] = vp[(size_t)r * HW + n0 + cc];
        }
        __syncthreads();
#pragma unroll 8
        for (int nn = 0; nn < 32; nn++) {
            float kc[4], vd[4];
#pragma unroll
            for (int i = 0; i < 4; i++) { kc[i] = Ks[cb + i][nn]; vd[i] = Vs[db + i][nn]; }
#pragma unroll
            for (int i = 0; i < 4; i++)
#pragma unroll
                for (int j = 0; j < 4; j++) acc[i][j] += kc[i] * vd[j];
        }
        __syncthreads();
    }
    float* cp = g_ctxp + ((size_t)(lga * 16 + b) * 8 + chunk) * 4096;
#pragma unroll
    for (int i = 0; i < 4; i++)
#pragma unroll
        for (int j = 0; j < 4; j++) cp[(cb + i) * 64 + db + j] = acc[i][j];
}

__global__ void ctxred_k()
{
    int i = blockIdx.x * 256 + threadIdx.x;
    if (i >= 2 * NB * 4096) return;
    int pair = i >> 12, e = i & 4095;
    const float* cp = g_ctxp + (size_t)pair * 8 * 4096 + e;
    float s = 0.f;
#pragma unroll
    for (int p = 0; p < 8; p++) s += cp[p * 4096];
    g_ctx[i] = s;
}

// ---------------- M[o,c] = sum_d Wproj[o,d] * ctx[c,d] ----------------
__global__ __launch_bounds__(256) void mproj_k(const float* __restrict__ Wp2, const float* __restrict__ Wp3)
{
    const int id = blockIdx.x;
    const int lga = id >> 4;
    const float* Wp = lga ? Wp3 : Wp2;
    const float* cx = g_ctx + (size_t)id * 4096;
    float* Mo = g_Mm + (size_t)id * 4096;
    for (int e = threadIdx.x; e < 4096; e += 256) {
        int o = e >> 6, c = e & 63;
        float s = 0.f;
#pragma unroll 16
        for (int d = 0; d < 64; d++) s += Wp[o * 64 + d] * cx[c * 64 + d];
        Mo[o * 64 + c] = s;
    }
}

// ---------------- final: out = relu( bn2(pout) + bn_sc(tsc) ) ----------------
__global__ __launch_bounds__(256) void final_k(float* __restrict__ out)
{
    size_t i = (size_t)blockIdx.x * 256 + threadIdx.x;
    int c = (int)((i >> 10) & 255);
    float s2 = g_scale[768 + c], h2 = g_shift[768 + c];
    float s0 = g_scale[c],       h0 = g_shift[c];
    float4 p = ((const float4*)g_pout)[i];
    float4 r = ((const float4*)g_tsc)[i];
    p.x = fmaxf(p.x * s2 + h2 + r.x * s0 + h0, 0.f);
    p.y = fmaxf(p.y * s2 + h2 + r.y * s0 + h0, 0.f);
    p.z = fmaxf(p.z * s2 + h2 + r.z * s0 + h0, 0.f);
    p.w = fmaxf(p.w * s2 + h2 + r.w * s0 + h0, 0.f);
    ((float4*)out)[i] = p;
}

// ---------------- launch ----------------
extern "C" void kernel_launch(void* const* d_in, const int* in_sizes, int n_in,
                              void* d_out, int out_size)
{
    (void)in_sizes; (void)n_in; (void)out_size;
    const float* x      = (const float*)d_in[0];
    const float* W_sc   = (const float*)d_in[1];
    const float* gsc    = (const float*)d_in[2];
    const float* bsc    = (const float*)d_in[3];
    const float* W1     = (const float*)d_in[4];
    const float* g1     = (const float*)d_in[5];
    const float* b1     = (const float*)d_in[6];
    const float* Wb0    = (const float*)d_in[7];
    const float* gb0    = (const float*)d_in[8];
    const float* bb0    = (const float*)d_in[9];
    const float* Wb1    = (const float*)d_in[10];
    const float* gb1    = (const float*)d_in[11];
    const float* bb1    = (const float*)d_in[12];
    const float* Wqkv2  = (const float*)d_in[13];
    const float* Wproj2 = (const float*)d_in[14];
    const float* ga2    = (const float*)d_in[15];
    const float* ba2    = (const float*)d_in[16];
    const float* Wqkv3  = (const float*)d_in[17];
    const float* Wproj3 = (const float*)d_in[18];
    const float* ga3    = (const float*)d_in[19];
    const float* ba3    = (const float*)d_in[20];
    const float* W2     = (const float*)d_in[21];
    const float* g2     = (const float*)d_in[22];
    const float* b2     = (const float*)d_in[23];

    float *tsc, *hh, *qk2, *qk3, *preB, *pout, *Mm;
    cudaGetSymbolAddress((void**)&tsc,  g_tsc);
    cudaGetSymbolAddress((void**)&hh,   g_h);
    cudaGetSymbolAddress((void**)&qk2,  g_qkv2);
    cudaGetSymbolAddress((void**)&qk3,  g_qkv3);
    cudaGetSymbolAddress((void**)&preB, g_preB);
    cudaGetSymbolAddress((void**)&pout, g_pout);
    cudaGetSymbolAddress((void**)&Mm,   g_Mm);

    // Stage 1: two 128->256 convs over x; stats fused into epilogues
    tgemm_k<<<dim3(32, 2, NB), 256, SMEMSZ128>>>(W_sc, x, tsc, 128, 0, (long)128 * HW, 0, (long)256 * HW, 0, -1, 0);
    tgemm_k<<<dim3(32, 2, NB), 256, SMEMSZ128>>>(W1,   x, hh,  128, 0, (long)128 * HW, 0, (long)256 * HW, 0, -1, 256);
    finalize_k<<<256, 256>>>(0,   gsc, bsc);
    finalize_k<<<256, 256>>>(256, g1,  b1);

    // Branch 0: 1x1 conv on s0 (BN of h folded into B loader)
    tgemm64_k<<<dim3(32, 1, NB), 256, SMEMSZ64>>>(Wb0, hh, preB, 64, 0, (long)256 * HW, 0, (long)256 * HW, 0, 256, 512);
    // Branch 1: 3x3 conv on s1 (implicit GEMM, BN folded)
    tconv_k<<<dim3(32, 1, NB), 256, SMEMSZ64>>>(Wb1);
    // Branches 2/3: qkv projections (BN folded; no stats), M=192 exact via 3 y-blocks
    tgemm64_k<<<dim3(32, 3, NB), 256, SMEMSZ64>>>(Wqkv2, hh, qk2, 64, 0, (long)256 * HW, 128, (long)192 * HW, 0, 256, -1);
    tgemm64_k<<<dim3(32, 3, NB), 256, SMEMSZ64>>>(Wqkv3, hh, qk3, 64, 0, (long)256 * HW, 192, (long)192 * HW, 0, 256, -1);
    softmax_k<<<2048, 256>>>(qk2, qk3);
    ctx_k<<<dim3(128, 2), 256>>>(qk2, qk3);
    ctxred_k<<<512, 256>>>();
    mproj_k<<<32, 256>>>(Wproj2, Wproj3);
    // attn output fused with proj: preB ch 128..191 / 192..255 = M[b] @ q[b]
    tgemm64_k<<<dim3(32, 1, NB), 256, SMEMSZ64>>>(Mm,                   qk2, preB, 64, 4096, (long)192 * HW, 0, (long)256 * HW, 128, -1, 512);
    tgemm64_k<<<dim3(32, 1, NB), 256, SMEMSZ64>>>(Mm + (size_t)NB*4096, qk3, preB, 64, 4096, (long)192 * HW, 0, (long)256 * HW, 192, -1, 512);

    // Branch BN params
    finalize_k<<<64, 256>>>(512, gb0, bb0);
    finalize_k<<<64, 256>>>(576, gb1, bb1);
    finalize_k<<<64, 256>>>(640, ga2, ba2);
    finalize_k<<<64, 256>>>(704, ga3, ba3);

    // Final 256->256 conv (BN of preB folded into B loader; stats fused)
    tgemm_k<<<dim3(32, 2, NB), 256, SMEMSZ128>>>(W2, preB, pout, 256, 0, (long)256 * HW, 0, (long)256 * HW, 0, 512, 768);
    finalize_k<<<256, 256>>>(768, g2, b2);
    final_k<<<16384, 256>>>((float*)d_out);
}